// round 3
// baseline (speedup 1.0000x reference)
#include <cuda_runtime.h>
#include <math.h>
#include <stdint.h>

// Problem constants
#define BATCH 2
#define TLEN 2048
#define MLEN 77
#define CDIM 512
#define HEADS 8
#define DHEAD 64
#define BT (BATCH * TLEN)      // 4096
#define NBIG (BT * CDIM)       // 2097152
#define NSMALL (BATCH * MLEN * CDIM) // 78848
#define MSMALL (BATCH * MLEN)  // 154

__device__ float g_scratch[8ULL * NBIG + 2ULL * NSMALL];

// ---------------------------------------------------------------------------
// tf32 helpers
// ---------------------------------------------------------------------------
__device__ __forceinline__ uint32_t f2tf32(float x) {
    uint32_t u;
    asm("cvt.rna.tf32.f32 %0, %1;" : "=r"(u) : "f"(x));
    return u;
}
__device__ __forceinline__ float f2tf32f(float x) {
    return __uint_as_float(f2tf32(x));
}

__device__ __forceinline__ void mma_m16n8k8(float (&d)[4],
    uint32_t a0, uint32_t a1, uint32_t a2, uint32_t a3,
    uint32_t b0, uint32_t b1)
{
    asm volatile(
        "mma.sync.aligned.m16n8k8.row.col.f32.tf32.tf32.f32 "
        "{%0,%1,%2,%3}, {%4,%5,%6,%7}, {%8,%9}, {%0,%1,%2,%3};\n"
        : "+f"(d[0]), "+f"(d[1]), "+f"(d[2]), "+f"(d[3])
        : "r"(a0), "r"(a1), "r"(a2), "r"(a3), "r"(b0), "r"(b1));
}

// ---------------------------------------------------------------------------
// tf32 GEMM core: out[m0:+128, n0:+128] = A[.,512] @ W[512,512] + bias
// 256 threads = 8 warps (4x2), warp tile 32x64, BK=16, double-buffered.
// sB is XOR-swizzled: col ^ (8*(k&3)) -> conflict-free B fragment loads.
// ---------------------------------------------------------------------------
__device__ __forceinline__ void gemm_core(const float* __restrict__ A,
    const float* __restrict__ W, const float* __restrict__ bias,
    float* __restrict__ out, int Mrows, int m0, int n0)
{
    __shared__ float sA[2][16][136];   // [k][m] stride 136 (conflict-free loads)
    __shared__ float sB[2][16][128];   // [k][n^swz]

    const int tid = threadIdx.x;
    const int lane = tid & 31;
    const int wid = tid >> 5;
    const int wm = (wid >> 1) * 32;
    const int wn = (wid & 1) * 64;
    const int g = lane >> 2;
    const int tg = lane & 3;

    const int ar = tid >> 1;
    const int akq = (tid & 1) * 8;
    const int bkr = tid >> 4;
    const int bn = (tid & 15) * 8;
    const int bcolsw = bn ^ (8 * (bkr & 3));

    // precomputed swizzled B fragment columns (constant over k)
    int bcol[8];
#pragma unroll
    for (int in = 0; in < 8; ++in)
        bcol[in] = (wn + in * 8 + g) ^ (8 * tg);

    float acc[2][8][4];
#pragma unroll
    for (int im = 0; im < 2; ++im)
#pragma unroll
        for (int in = 0; in < 8; ++in)
#pragma unroll
            for (int j = 0; j < 4; ++j) acc[im][in][j] = 0.f;

    const bool arow_ok = (m0 + ar) < Mrows;
    const float* aptr = A + (size_t)(m0 + ar) * 512 + akq;
    const float* wptr = W + (size_t)bkr * 512 + n0 + bn;

    float4 ra0, ra1, rb0, rb1;

    auto load_stage = [&](int k0) {
        if (arow_ok) {
            ra0 = *reinterpret_cast<const float4*>(aptr + k0);
            ra1 = *reinterpret_cast<const float4*>(aptr + k0 + 4);
        } else {
            ra0 = make_float4(0.f, 0.f, 0.f, 0.f);
            ra1 = ra0;
        }
        rb0 = *reinterpret_cast<const float4*>(wptr + (size_t)k0 * 512);
        rb1 = *reinterpret_cast<const float4*>(wptr + (size_t)k0 * 512 + 4);
    };
    auto store_stage = [&](int buf) {
        sA[buf][akq + 0][ar] = f2tf32f(ra0.x);
        sA[buf][akq + 1][ar] = f2tf32f(ra0.y);
        sA[buf][akq + 2][ar] = f2tf32f(ra0.z);
        sA[buf][akq + 3][ar] = f2tf32f(ra0.w);
        sA[buf][akq + 4][ar] = f2tf32f(ra1.x);
        sA[buf][akq + 5][ar] = f2tf32f(ra1.y);
        sA[buf][akq + 6][ar] = f2tf32f(ra1.z);
        sA[buf][akq + 7][ar] = f2tf32f(ra1.w);
        float4 c0 = make_float4(f2tf32f(rb0.x), f2tf32f(rb0.y), f2tf32f(rb0.z), f2tf32f(rb0.w));
        float4 c1 = make_float4(f2tf32f(rb1.x), f2tf32f(rb1.y), f2tf32f(rb1.z), f2tf32f(rb1.w));
        *reinterpret_cast<float4*>(&sB[buf][bkr][bcolsw]) = c0;
        *reinterpret_cast<float4*>(&sB[buf][bkr][bcolsw + 4]) = c1;
    };

    load_stage(0);
    store_stage(0);
    __syncthreads();

#pragma unroll 1
    for (int it = 0; it < 32; ++it) {
        const int buf = it & 1;
        if (it < 31) load_stage((it + 1) * 16);

#pragma unroll
        for (int kk = 0; kk < 16; kk += 8) {
            uint32_t af[2][4];
#pragma unroll
            for (int im = 0; im < 2; ++im) {
                af[im][0] = __float_as_uint(sA[buf][kk + tg    ][wm + im * 16 + g    ]);
                af[im][1] = __float_as_uint(sA[buf][kk + tg    ][wm + im * 16 + g + 8]);
                af[im][2] = __float_as_uint(sA[buf][kk + tg + 4][wm + im * 16 + g    ]);
                af[im][3] = __float_as_uint(sA[buf][kk + tg + 4][wm + im * 16 + g + 8]);
            }
#pragma unroll
            for (int in = 0; in < 8; ++in) {
                const uint32_t b0 = __float_as_uint(sB[buf][kk + tg    ][bcol[in]]);
                const uint32_t b1 = __float_as_uint(sB[buf][kk + tg + 4][bcol[in]]);
#pragma unroll
                for (int im = 0; im < 2; ++im)
                    mma_m16n8k8(acc[im][in], af[im][0], af[im][1], af[im][2], af[im][3], b0, b1);
            }
        }

        if (it < 31) {
            store_stage(1 - buf);
            __syncthreads();
        }
    }

#pragma unroll
    for (int in = 0; in < 8; ++in) {
        const int col = n0 + wn + in * 8 + tg * 2;
        const float2 bb = *reinterpret_cast<const float2*>(bias + col);
#pragma unroll
        for (int im = 0; im < 2; ++im) {
            const int r0 = m0 + wm + im * 16 + g;
            if (r0 < Mrows) {
                float2 v = make_float2(acc[im][in][0] + bb.x, acc[im][in][1] + bb.y);
                *reinterpret_cast<float2*>(out + (size_t)r0 * 512 + col) = v;
            }
            const int r1 = r0 + 8;
            if (r1 < Mrows) {
                float2 v = make_float2(acc[im][in][2] + bb.x, acc[im][in][3] + bb.y);
                *reinterpret_cast<float2*>(out + (size_t)r1 * 512 + col) = v;
            }
        }
    }
}

// Fused projections: Q,K,V (3 x 128) + KC,VC (2 x 8) = 400 blocks
__global__ __launch_bounds__(256) void proj_kernel(
    const float* __restrict__ x, const float* __restrict__ c,
    const float* __restrict__ Wq, const float* __restrict__ bq,
    const float* __restrict__ Wk, const float* __restrict__ bk,
    const float* __restrict__ Wv, const float* __restrict__ bv,
    const float* __restrict__ Wkc, const float* __restrict__ bkc,
    const float* __restrict__ Wvc, const float* __restrict__ bvc,
    float* __restrict__ Qb, float* __restrict__ Kb, float* __restrict__ Vb,
    float* __restrict__ KCb, float* __restrict__ VCb)
{
    const int bid = blockIdx.x;
    const float *A, *W, *bias;
    float* out;
    int Mrows, m0, n0;
    if (bid < 384) {
        const int t = bid / 128, l = bid % 128;
        m0 = (l >> 2) * 128;
        n0 = (l & 3) * 128;
        A = x; Mrows = BT;
        W = (t == 0) ? Wq : ((t == 1) ? Wk : Wv);
        bias = (t == 0) ? bq : ((t == 1) ? bk : bv);
        out = (t == 0) ? Qb : ((t == 1) ? Kb : Vb);
    } else {
        const int r = bid - 384;
        const int t = r / 8, l = r % 8;
        m0 = (l >> 2) * 128;
        n0 = (l & 3) * 128;
        A = c; Mrows = MSMALL;
        W = t ? Wvc : Wkc;
        bias = t ? bvc : bkc;
        out = t ? VCb : KCb;
    }
    gemm_core(A, W, bias, out, Mrows, m0, n0);
}

__global__ __launch_bounds__(256) void gates_kernel(
    const float* __restrict__ Yb, const float* __restrict__ YCb,
    const float* __restrict__ Wg1, const float* __restrict__ bg1,
    const float* __restrict__ Wg2, const float* __restrict__ bg2,
    float* __restrict__ G1, float* __restrict__ G2)
{
    const int bid = blockIdx.x;
    const int t = bid >> 7;
    const int l = bid & 127;
    const int m0 = (l >> 2) * 128;
    const int n0 = (l & 3) * 128;
    gemm_core(t ? YCb : Yb, t ? Wg2 : Wg1, t ? bg2 : bg1, t ? G2 : G1, BT, m0, n0);
}

__global__ __launch_bounds__(256) void final_gemm_kernel(
    const float* __restrict__ F, const float* __restrict__ Wp,
    const float* __restrict__ bp, float* __restrict__ out)
{
    const int l = blockIdx.x;
    const int m0 = (l >> 2) * 128;
    const int n0 = (l & 3) * 128;
    gemm_core(F, Wp, bp, out, BT, m0, n0);
}

// ---------------------------------------------------------------------------
// Flash self-attention (causal), tf32 mma. 128 queries/block, 8 warps
// (warp = 16 rows), 64-key tiles. Q pre-scaled by 1/8. sV XOR-swizzled.
// grid: (T/128, B*H) with qb reversed for heavy-first scheduling.
// ---------------------------------------------------------------------------
#define SQS 76

__global__ __launch_bounds__(256) void self_attn_mma(
    const float* __restrict__ Q, const float* __restrict__ K,
    const float* __restrict__ V, float* __restrict__ Y)
{
    extern __shared__ float sm[];
    float* sQ = sm;                      // [128][76]
    float* sP = sQ + 128 * SQS;          // [128][76]
    float* sK = sP + 128 * SQS;          // [64][76]
    float* sV = sK + 64 * SQS;           // [64][64] swizzled

    const int qb = (int)gridDim.x - 1 - (int)blockIdx.x;  // heavy blocks first
    const int bh = blockIdx.y;
    const int b = bh >> 3;
    const int h = bh & 7;
    const int tid = threadIdx.x;
    const int lane = tid & 31;
    const int wid = tid >> 5;
    const int g = lane >> 2;
    const int tg = lane & 3;

    const size_t base = ((size_t)b * TLEN) * CDIM + h * DHEAD;

    // load + scale + tf32 Q tile (128 x 64), float4 staging
    for (int i = tid; i < 128 * 16; i += 256) {
        const int r = i >> 4, c4 = (i & 15) * 4;
        const float4 q = *reinterpret_cast<const float4*>(
            Q + base + (size_t)(qb * 128 + r) * CDIM + c4);
        float* dst = &sQ[r * SQS + c4];
        dst[0] = f2tf32f(q.x * 0.125f);
        dst[1] = f2tf32f(q.y * 0.125f);
        dst[2] = f2tf32f(q.z * 0.125f);
        dst[3] = f2tf32f(q.w * 0.125f);
    }

    float o[8][4];
#pragma unroll
    for (int in = 0; in < 8; ++in)
#pragma unroll
        for (int j = 0; j < 4; ++j) o[in][j] = 0.f;
    float mrow[2] = {-1e30f, -1e30f};
    float lrow[2] = {0.f, 0.f};

    const int rA = wid * 16 + g;
    const int qrA = qb * 128 + rA;
    const int qrB = qrA + 8;

    int bcolV[8];
#pragma unroll
    for (int in = 0; in < 8; ++in)
        bcolV[in] = (in * 8 + g) ^ (8 * tg);

    const int nIter = 2 * (qb + 1);
    for (int jt = 0; jt < nIter; ++jt) {
        __syncthreads();
        // stage K (row-major, stride 76) and V (swizzled [k][n])
        for (int i = tid; i < 64 * 16; i += 256) {
            const int r = i >> 4, c4 = (i & 15) * 4;
            const size_t gidx = base + (size_t)(jt * 64 + r) * CDIM + c4;
            const float4 kv = *reinterpret_cast<const float4*>(K + gidx);
            const float4 vv = *reinterpret_cast<const float4*>(V + gidx);
            float* kd = &sK[r * SQS + c4];
            kd[0] = f2tf32f(kv.x);
            kd[1] = f2tf32f(kv.y);
            kd[2] = f2tf32f(kv.z);
            kd[3] = f2tf32f(kv.w);
            const int vc = c4 ^ (8 * (r & 3));
            *reinterpret_cast<float4*>(&sV[r * 64 + vc]) =
                make_float4(f2tf32f(vv.x), f2tf32f(vv.y), f2tf32f(vv.z), f2tf32f(vv.w));
        }
        __syncthreads();

        // S = Q @ K^T
        float s[8][4];
#pragma unroll
        for (int in = 0; in < 8; ++in)
#pragma unroll
            for (int j = 0; j < 4; ++j) s[in][j] = 0.f;

#pragma unroll
        for (int kk = 0; kk < 64; kk += 8) {
            const uint32_t a0 = __float_as_uint(sQ[(rA    ) * SQS + kk + tg    ]);
            const uint32_t a1 = __float_as_uint(sQ[(rA + 8) * SQS + kk + tg    ]);
            const uint32_t a2 = __float_as_uint(sQ[(rA    ) * SQS + kk + tg + 4]);
            const uint32_t a3 = __float_as_uint(sQ[(rA + 8) * SQS + kk + tg + 4]);
#pragma unroll
            for (int in = 0; in < 8; ++in) {
                const uint32_t b0 = __float_as_uint(sK[(in * 8 + g) * SQS + kk + tg    ]);
                const uint32_t b1 = __float_as_uint(sK[(in * 8 + g) * SQS + kk + tg + 4]);
                mma_m16n8k8(s[in], a0, a1, a2, a3, b0, b1);
            }
        }

        // causal mask on diagonal tiles
        if (jt >= 2 * qb) {
#pragma unroll
            for (int in = 0; in < 8; ++in) {
                const int cj = jt * 64 + in * 8 + tg * 2;
                if (cj     > qrA) s[in][0] = -1e30f;
                if (cj + 1 > qrA) s[in][1] = -1e30f;
                if (cj     > qrB) s[in][2] = -1e30f;
                if (cj + 1 > qrB) s[in][3] = -1e30f;
            }
        }

        // online softmax
        float rmA = -1e30f, rmB = -1e30f;
#pragma unroll
        for (int in = 0; in < 8; ++in) {
            rmA = fmaxf(rmA, fmaxf(s[in][0], s[in][1]));
            rmB = fmaxf(rmB, fmaxf(s[in][2], s[in][3]));
        }
        rmA = fmaxf(rmA, __shfl_xor_sync(0xffffffffu, rmA, 1));
        rmA = fmaxf(rmA, __shfl_xor_sync(0xffffffffu, rmA, 2));
        rmB = fmaxf(rmB, __shfl_xor_sync(0xffffffffu, rmB, 1));
        rmB = fmaxf(rmB, __shfl_xor_sync(0xffffffffu, rmB, 2));

        const float mA = fmaxf(mrow[0], rmA);
        const float mB = fmaxf(mrow[1], rmB);
        const float cA = __expf(mrow[0] - mA);
        const float cB = __expf(mrow[1] - mB);

        float rsA = 0.f, rsB = 0.f;
#pragma unroll
        for (int in = 0; in < 8; ++in) {
            const float p0 = __expf(s[in][0] - mA);
            const float p1 = __expf(s[in][1] - mA);
            const float p2 = __expf(s[in][2] - mB);
            const float p3 = __expf(s[in][3] - mB);
            rsA += p0 + p1;
            rsB += p2 + p3;
            const int col = in * 8 + tg * 2;
            *reinterpret_cast<float2*>(&sP[(rA    ) * SQS + col]) =
                make_float2(f2tf32f(p0), f2tf32f(p1));
            *reinterpret_cast<float2*>(&sP[(rA + 8) * SQS + col]) =
                make_float2(f2tf32f(p2), f2tf32f(p3));
        }
        rsA += __shfl_xor_sync(0xffffffffu, rsA, 1);
        rsA += __shfl_xor_sync(0xffffffffu, rsA, 2);
        rsB += __shfl_xor_sync(0xffffffffu, rsB, 1);
        rsB += __shfl_xor_sync(0xffffffffu, rsB, 2);

        lrow[0] = lrow[0] * cA + rsA;
        lrow[1] = lrow[1] * cB + rsB;
        mrow[0] = mA;
        mrow[1] = mB;

#pragma unroll
        for (int in = 0; in < 8; ++in) {
            o[in][0] *= cA;
            o[in][1] *= cA;
            o[in][2] *= cB;
            o[in][3] *= cB;
        }
        __syncwarp();

        // O += P @ V (sV swizzled -> conflict-free)
#pragma unroll
        for (int kk = 0; kk < 64; kk += 8) {
            const uint32_t a0 = __float_as_uint(sP[(rA    ) * SQS + kk + tg    ]);
            const uint32_t a1 = __float_as_uint(sP[(rA + 8) * SQS + kk + tg    ]);
            const uint32_t a2 = __float_as_uint(sP[(rA    ) * SQS + kk + tg + 4]);
            const uint32_t a3 = __float_as_uint(sP[(rA + 8) * SQS + kk + tg + 4]);
#pragma unroll
            for (int in = 0; in < 8; ++in) {
                const uint32_t b0 = __float_as_uint(sV[(kk + tg    ) * 64 + bcolV[in]]);
                const uint32_t b1 = __float_as_uint(sV[(kk + tg + 4) * 64 + bcolV[in]]);
                mma_m16n8k8(o[in], a0, a1, a2, a3, b0, b1);
            }
        }
    }

    const float invA = 1.f / lrow[0];
    const float invB = 1.f / lrow[1];
#pragma unroll
    for (int in = 0; in < 8; ++in) {
        const int col = in * 8 + tg * 2;
        *reinterpret_cast<float2*>(Y + base + (size_t)qrA * CDIM + col) =
            make_float2(o[in][0] * invA, o[in][1] * invA);
        *reinterpret_cast<float2*>(Y + base + (size_t)qrB * CDIM + col) =
            make_float2(o[in][2] * invB, o[in][3] * invB);
    }
}

// ---------------------------------------------------------------------------
// Cross-attention: 77 keys/head, padding mask. One thread per query row.
// ---------------------------------------------------------------------------
__global__ __launch_bounds__(128) void cross_attn_kernel(
    const float* __restrict__ Q, const float* __restrict__ Kc,
    const float* __restrict__ Vc, const int* __restrict__ pad,
    float* __restrict__ Yc)
{
    const int bh = blockIdx.y;
    const int b = bh >> 3;
    const int h = bh & 7;
    const int row0 = blockIdx.x * 128;
    const int tid = threadIdx.x;

    __shared__ float sQ[128 * 65];

    const size_t qbase = ((size_t)b * TLEN) * CDIM + h * DHEAD;
    for (int i = tid; i < 128 * 64; i += 128) {
        const int r = i >> 6, c = i & 63;
        sQ[r * 65 + c] = Q[qbase + (size_t)(row0 + r) * CDIM + c];
    }
    __syncthreads();

    const float* kb = Kc + ((size_t)b * MLEN) * CDIM + h * DHEAD;
    const float* vb = Vc + ((size_t)b * MLEN) * CDIM + h * DHEAD;
    const int* pb = pad + b * MLEN;
    const float* qrow = &sQ[tid * 65];

    float m = -1e30f;
    for (int j = 0; j < MLEN; ++j) {
        if (pb[j] == 0) continue;
        float dot = 0.f;
        const float* kr = kb + (size_t)j * CDIM;
#pragma unroll 16
        for (int d = 0; d < 64; ++d) dot = fmaf(qrow[d], kr[d], dot);
        m = fmaxf(m, dot * 0.125f);
    }

    float l = 0.f;
    float o[64];
#pragma unroll
    for (int d = 0; d < 64; ++d) o[d] = 0.f;

    for (int j = 0; j < MLEN; ++j) {
        if (pb[j] == 0) continue;
        float dot = 0.f;
        const float* kr = kb + (size_t)j * CDIM;
#pragma unroll 16
        for (int d = 0; d < 64; ++d) dot = fmaf(qrow[d], kr[d], dot);
        const float p = __expf(dot * 0.125f - m);
        l += p;
        const float* vr = vb + (size_t)j * CDIM;
#pragma unroll 16
        for (int d = 0; d < 64; ++d) o[d] = fmaf(p, vr[d], o[d]);
    }

    const float inv = (l > 0.f) ? (1.f / l) : 0.f;
    float* yout = Yc + qbase + (size_t)(row0 + tid) * CDIM;
#pragma unroll 16
    for (int d = 0; d < 64; ++d) yout[d] = o[d] * inv;
}

// ---------------------------------------------------------------------------
// fused = sigmoid(g1) * yc + sigmoid(g2) * y
// ---------------------------------------------------------------------------
__device__ __forceinline__ float sigf(float x) {
    return 1.f / (1.f + __expf(-x));
}

__global__ __launch_bounds__(256) void gate_fuse_kernel(
    const float* __restrict__ g1, const float* __restrict__ g2,
    const float* __restrict__ y, const float* __restrict__ yc,
    float* __restrict__ out)
{
    const int i = blockIdx.x * blockDim.x + threadIdx.x;
    const float4 a = reinterpret_cast<const float4*>(g1)[i];
    const float4 bg = reinterpret_cast<const float4*>(g2)[i];
    const float4 yv = reinterpret_cast<const float4*>(y)[i];
    const float4 yw = reinterpret_cast<const float4*>(yc)[i];
    float4 o;
    o.x = sigf(a.x) * yw.x + sigf(bg.x) * yv.x;
    o.y = sigf(a.y) * yw.y + sigf(bg.y) * yv.y;
    o.z = sigf(a.z) * yw.z + sigf(bg.z) * yv.z;
    o.w = sigf(a.w) * yw.w + sigf(bg.w) * yv.w;
    reinterpret_cast<float4*>(out)[i] = o;
}

// ---------------------------------------------------------------------------
// Launch
// ---------------------------------------------------------------------------
extern "C" void kernel_launch(void* const* d_in, const int* in_sizes, int n_in,
                              void* d_out, int out_size)
{
    const float* x  = (const float*)d_in[0];
    const float* c  = (const float*)d_in[1];
    const int* pad  = (const int*)d_in[3];
    const float* Wq = (const float*)d_in[4];
    const float* bq = (const float*)d_in[5];
    const float* Wk = (const float*)d_in[6];
    const float* bk = (const float*)d_in[7];
    const float* Wv = (const float*)d_in[8];
    const float* bv = (const float*)d_in[9];
    const float* Wkc = (const float*)d_in[10];
    const float* bkc = (const float*)d_in[11];
    const float* Wvc = (const float*)d_in[12];
    const float* bvc = (const float*)d_in[13];
    const float* Wg1 = (const float*)d_in[14];
    const float* bg1 = (const float*)d_in[15];
    const float* Wg2 = (const float*)d_in[16];
    const float* bg2 = (const float*)d_in[17];
    const float* Wp = (const float*)d_in[18];
    const float* bp = (const float*)d_in[19];
    float* out = (float*)d_out;

    float* S = nullptr;
    cudaGetSymbolAddress((void**)&S, g_scratch);
    float* Qb  = S + 0ULL * NBIG;
    float* Kb  = S + 1ULL * NBIG;
    float* Vb  = S + 2ULL * NBIG;
    float* Yb  = S + 3ULL * NBIG;
    float* YCb = S + 4ULL * NBIG;
    float* G1b = S + 5ULL * NBIG;
    float* G2b = S + 6ULL * NBIG;
    float* Fb  = S + 7ULL * NBIG;
    float* KCb = S + 8ULL * NBIG;
    float* VCb = S + 8ULL * NBIG + NSMALL;

    const int SMEM_SA = (256 * SQS + 64 * SQS + 64 * 64) * (int)sizeof(float); // 113664
    cudaFuncSetAttribute(self_attn_mma,
                         cudaFuncAttributeMaxDynamicSharedMemorySize, SMEM_SA);

    proj_kernel<<<400, 256>>>(x, c, Wq, bq, Wk, bk, Wv, bv,
                              Wkc, bkc, Wvc, bvc, Qb, Kb, Vb, KCb, VCb);

    self_attn_mma<<<dim3(TLEN / 128, BATCH * HEADS), 256, SMEM_SA>>>(Qb, Kb, Vb, Yb);
    cross_attn_kernel<<<dim3(TLEN / 128, BATCH * HEADS), 128>>>(Qb, KCb, VCb, pad, YCb);

    gates_kernel<<<256, 256>>>(Yb, YCb, Wg1, bg1, Wg2, bg2, G1b, G2b);
    gate_fuse_kernel<<<NBIG / 4 / 256, 256>>>(G1b, G2b, Yb, YCb, Fb);
    final_gemm_kernel<<<128, 256>>>(Fb, Wp, bp, out);
}

// round 4
// speedup vs baseline: 1.0481x; 1.0481x over previous
#include <cuda_runtime.h>
#include <math.h>
#include <stdint.h>

// Problem constants
#define BATCH 2
#define TLEN 2048
#define MLEN 77
#define CDIM 512
#define HEADS 8
#define DHEAD 64
#define BT (BATCH * TLEN)      // 4096
#define NBIG (BT * CDIM)       // 2097152
#define NSMALL (BATCH * MLEN * CDIM) // 78848
#define MSMALL (BATCH * MLEN)  // 154

__device__ float g_scratch[8ULL * NBIG + 2ULL * NSMALL];

// ---------------------------------------------------------------------------
// tf32 helpers
// ---------------------------------------------------------------------------
__device__ __forceinline__ uint32_t f2tf32(float x) {
    uint32_t u;
    asm("cvt.rna.tf32.f32 %0, %1;" : "=r"(u) : "f"(x));
    return u;
}
__device__ __forceinline__ float f2tf32f(float x) {
    return __uint_as_float(f2tf32(x));
}

__device__ __forceinline__ void mma_m16n8k8(float (&d)[4],
    uint32_t a0, uint32_t a1, uint32_t a2, uint32_t a3,
    uint32_t b0, uint32_t b1)
{
    asm volatile(
        "mma.sync.aligned.m16n8k8.row.col.f32.tf32.tf32.f32 "
        "{%0,%1,%2,%3}, {%4,%5,%6,%7}, {%8,%9}, {%0,%1,%2,%3};\n"
        : "+f"(d[0]), "+f"(d[1]), "+f"(d[2]), "+f"(d[3])
        : "r"(a0), "r"(a1), "r"(a2), "r"(a3), "r"(b0), "r"(b1));
}

// ---------------------------------------------------------------------------
// tf32 GEMM core: out[m0:+128, n0:+128] = A[.,512] @ W[512,512] + bias
// 256 threads = 8 warps (4x2), warp tile 32x64, BK=16, double-buffered.
// sB is XOR-swizzled: col ^ (8*(k&3)) -> conflict-free B fragment loads.
// ---------------------------------------------------------------------------
__device__ __forceinline__ void gemm_core(const float* __restrict__ A,
    const float* __restrict__ W, const float* __restrict__ bias,
    float* __restrict__ out, int Mrows, int m0, int n0)
{
    __shared__ float sA[2][16][136];   // [k][m] stride 136 (conflict-free loads)
    __shared__ float sB[2][16][128];   // [k][n^swz]

    const int tid = threadIdx.x;
    const int lane = tid & 31;
    const int wid = tid >> 5;
    const int wm = (wid >> 1) * 32;
    const int wn = (wid & 1) * 64;
    const int g = lane >> 2;
    const int tg = lane & 3;

    const int ar = tid >> 1;
    const int akq = (tid & 1) * 8;
    const int bkr = tid >> 4;
    const int bn = (tid & 15) * 8;
    const int bcolsw = bn ^ (8 * (bkr & 3));

    // precomputed swizzled B fragment columns (constant over k)
    int bcol[8];
#pragma unroll
    for (int in = 0; in < 8; ++in)
        bcol[in] = (wn + in * 8 + g) ^ (8 * tg);

    float acc[2][8][4];
#pragma unroll
    for (int im = 0; im < 2; ++im)
#pragma unroll
        for (int in = 0; in < 8; ++in)
#pragma unroll
            for (int j = 0; j < 4; ++j) acc[im][in][j] = 0.f;

    const bool arow_ok = (m0 + ar) < Mrows;
    const float* aptr = A + (size_t)(m0 + ar) * 512 + akq;
    const float* wptr = W + (size_t)bkr * 512 + n0 + bn;

    float4 ra0, ra1, rb0, rb1;

    auto load_stage = [&](int k0) {
        if (arow_ok) {
            ra0 = *reinterpret_cast<const float4*>(aptr + k0);
            ra1 = *reinterpret_cast<const float4*>(aptr + k0 + 4);
        } else {
            ra0 = make_float4(0.f, 0.f, 0.f, 0.f);
            ra1 = ra0;
        }
        rb0 = *reinterpret_cast<const float4*>(wptr + (size_t)k0 * 512);
        rb1 = *reinterpret_cast<const float4*>(wptr + (size_t)k0 * 512 + 4);
    };
    auto store_stage = [&](int buf) {
        sA[buf][akq + 0][ar] = f2tf32f(ra0.x);
        sA[buf][akq + 1][ar] = f2tf32f(ra0.y);
        sA[buf][akq + 2][ar] = f2tf32f(ra0.z);
        sA[buf][akq + 3][ar] = f2tf32f(ra0.w);
        sA[buf][akq + 4][ar] = f2tf32f(ra1.x);
        sA[buf][akq + 5][ar] = f2tf32f(ra1.y);
        sA[buf][akq + 6][ar] = f2tf32f(ra1.z);
        sA[buf][akq + 7][ar] = f2tf32f(ra1.w);
        float4 c0 = make_float4(f2tf32f(rb0.x), f2tf32f(rb0.y), f2tf32f(rb0.z), f2tf32f(rb0.w));
        float4 c1 = make_float4(f2tf32f(rb1.x), f2tf32f(rb1.y), f2tf32f(rb1.z), f2tf32f(rb1.w));
        *reinterpret_cast<float4*>(&sB[buf][bkr][bcolsw]) = c0;
        *reinterpret_cast<float4*>(&sB[buf][bkr][bcolsw + 4]) = c1;
    };

    load_stage(0);
    store_stage(0);
    __syncthreads();

#pragma unroll 1
    for (int it = 0; it < 32; ++it) {
        const int buf = it & 1;
        if (it < 31) load_stage((it + 1) * 16);

#pragma unroll
        for (int kk = 0; kk < 16; kk += 8) {
            uint32_t af[2][4];
#pragma unroll
            for (int im = 0; im < 2; ++im) {
                af[im][0] = __float_as_uint(sA[buf][kk + tg    ][wm + im * 16 + g    ]);
                af[im][1] = __float_as_uint(sA[buf][kk + tg    ][wm + im * 16 + g + 8]);
                af[im][2] = __float_as_uint(sA[buf][kk + tg + 4][wm + im * 16 + g    ]);
                af[im][3] = __float_as_uint(sA[buf][kk + tg + 4][wm + im * 16 + g + 8]);
            }
#pragma unroll
            for (int in = 0; in < 8; ++in) {
                const uint32_t b0 = __float_as_uint(sB[buf][kk + tg    ][bcol[in]]);
                const uint32_t b1 = __float_as_uint(sB[buf][kk + tg + 4][bcol[in]]);
#pragma unroll
                for (int im = 0; im < 2; ++im)
                    mma_m16n8k8(acc[im][in], af[im][0], af[im][1], af[im][2], af[im][3], b0, b1);
            }
        }

        if (it < 31) {
            store_stage(1 - buf);
            __syncthreads();
        }
    }

#pragma unroll
    for (int in = 0; in < 8; ++in) {
        const int col = n0 + wn + in * 8 + tg * 2;
        const float2 bb = *reinterpret_cast<const float2*>(bias + col);
#pragma unroll
        for (int im = 0; im < 2; ++im) {
            const int r0 = m0 + wm + im * 16 + g;
            if (r0 < Mrows) {
                float2 v = make_float2(acc[im][in][0] + bb.x, acc[im][in][1] + bb.y);
                *reinterpret_cast<float2*>(out + (size_t)r0 * 512 + col) = v;
            }
            const int r1 = r0 + 8;
            if (r1 < Mrows) {
                float2 v = make_float2(acc[im][in][2] + bb.x, acc[im][in][3] + bb.y);
                *reinterpret_cast<float2*>(out + (size_t)r1 * 512 + col) = v;
            }
        }
    }
}

// Fused projections: Q,K,V (3 x 128) + KC,VC (2 x 8) = 400 blocks
__global__ __launch_bounds__(256) void proj_kernel(
    const float* __restrict__ x, const float* __restrict__ c,
    const float* __restrict__ Wq, const float* __restrict__ bq,
    const float* __restrict__ Wk, const float* __restrict__ bk,
    const float* __restrict__ Wv, const float* __restrict__ bv,
    const float* __restrict__ Wkc, const float* __restrict__ bkc,
    const float* __restrict__ Wvc, const float* __restrict__ bvc,
    float* __restrict__ Qb, float* __restrict__ Kb, float* __restrict__ Vb,
    float* __restrict__ KCb, float* __restrict__ VCb)
{
    const int bid = blockIdx.x;
    const float *A, *W, *bias;
    float* out;
    int Mrows, m0, n0;
    if (bid < 384) {
        const int t = bid / 128, l = bid % 128;
        m0 = (l >> 2) * 128;
        n0 = (l & 3) * 128;
        A = x; Mrows = BT;
        W = (t == 0) ? Wq : ((t == 1) ? Wk : Wv);
        bias = (t == 0) ? bq : ((t == 1) ? bk : bv);
        out = (t == 0) ? Qb : ((t == 1) ? Kb : Vb);
    } else {
        const int r = bid - 384;
        const int t = r / 8, l = r % 8;
        m0 = (l >> 2) * 128;
        n0 = (l & 3) * 128;
        A = c; Mrows = MSMALL;
        W = t ? Wvc : Wkc;
        bias = t ? bvc : bkc;
        out = t ? VCb : KCb;
    }
    gemm_core(A, W, bias, out, Mrows, m0, n0);
}

__global__ __launch_bounds__(256) void gates_kernel(
    const float* __restrict__ Yb, const float* __restrict__ YCb,
    const float* __restrict__ Wg1, const float* __restrict__ bg1,
    const float* __restrict__ Wg2, const float* __restrict__ bg2,
    float* __restrict__ G1, float* __restrict__ G2)
{
    const int bid = blockIdx.x;
    const int t = bid >> 7;
    const int l = bid & 127;
    const int m0 = (l >> 2) * 128;
    const int n0 = (l & 3) * 128;
    gemm_core(t ? YCb : Yb, t ? Wg2 : Wg1, t ? bg2 : bg1, t ? G2 : G1, BT, m0, n0);
}

__global__ __launch_bounds__(256) void final_gemm_kernel(
    const float* __restrict__ F, const float* __restrict__ Wp,
    const float* __restrict__ bp, float* __restrict__ out)
{
    const int l = blockIdx.x;
    const int m0 = (l >> 2) * 128;
    const int n0 = (l & 3) * 128;
    gemm_core(F, Wp, bp, out, BT, m0, n0);
}

// ---------------------------------------------------------------------------
// Flash self-attention (causal), tf32 mma. 128 queries/block, 8 warps
// (warp = 16 rows), 64-key tiles. Q pre-scaled by 1/8. sV XOR-swizzled.
// grid: (T/128, B*H) with qb reversed for heavy-first scheduling.
// ---------------------------------------------------------------------------
#define SQS 76

__global__ __launch_bounds__(256) void self_attn_mma(
    const float* __restrict__ Q, const float* __restrict__ K,
    const float* __restrict__ V, float* __restrict__ Y)
{
    extern __shared__ float sm[];
    float* sQ = sm;                      // [128][76]
    float* sP = sQ + 128 * SQS;          // [128][76]
    float* sK = sP + 128 * SQS;          // [64][76]
    float* sV = sK + 64 * SQS;           // [64][64] swizzled

    const int qb = (int)gridDim.x - 1 - (int)blockIdx.x;  // heavy blocks first
    const int bh = blockIdx.y;
    const int b = bh >> 3;
    const int h = bh & 7;
    const int tid = threadIdx.x;
    const int lane = tid & 31;
    const int wid = tid >> 5;
    const int g = lane >> 2;
    const int tg = lane & 3;

    const size_t base = ((size_t)b * TLEN) * CDIM + h * DHEAD;

    // load + scale + tf32 Q tile (128 x 64), float4 staging
    for (int i = tid; i < 128 * 16; i += 256) {
        const int r = i >> 4, c4 = (i & 15) * 4;
        const float4 q = *reinterpret_cast<const float4*>(
            Q + base + (size_t)(qb * 128 + r) * CDIM + c4);
        float* dst = &sQ[r * SQS + c4];
        dst[0] = f2tf32f(q.x * 0.125f);
        dst[1] = f2tf32f(q.y * 0.125f);
        dst[2] = f2tf32f(q.z * 0.125f);
        dst[3] = f2tf32f(q.w * 0.125f);
    }

    float o[8][4];
#pragma unroll
    for (int in = 0; in < 8; ++in)
#pragma unroll
        for (int j = 0; j < 4; ++j) o[in][j] = 0.f;
    float mrow[2] = {-1e30f, -1e30f};
    float lrow[2] = {0.f, 0.f};

    const int rA = wid * 16 + g;
    const int qrA = qb * 128 + rA;
    const int qrB = qrA + 8;

    int bcolV[8];
#pragma unroll
    for (int in = 0; in < 8; ++in)
        bcolV[in] = (in * 8 + g) ^ (8 * tg);

    const int nIter = 2 * (qb + 1);
    for (int jt = 0; jt < nIter; ++jt) {
        __syncthreads();
        // stage K (row-major, stride 76) and V (swizzled [k][n])
        for (int i = tid; i < 64 * 16; i += 256) {
            const int r = i >> 4, c4 = (i & 15) * 4;
            const size_t gidx = base + (size_t)(jt * 64 + r) * CDIM + c4;
            const float4 kv = *reinterpret_cast<const float4*>(K + gidx);
            const float4 vv = *reinterpret_cast<const float4*>(V + gidx);
            float* kd = &sK[r * SQS + c4];
            kd[0] = f2tf32f(kv.x);
            kd[1] = f2tf32f(kv.y);
            kd[2] = f2tf32f(kv.z);
            kd[3] = f2tf32f(kv.w);
            const int vc = c4 ^ (8 * (r & 3));
            *reinterpret_cast<float4*>(&sV[r * 64 + vc]) =
                make_float4(f2tf32f(vv.x), f2tf32f(vv.y), f2tf32f(vv.z), f2tf32f(vv.w));
        }
        __syncthreads();

        // S = Q @ K^T
        float s[8][4];
#pragma unroll
        for (int in = 0; in < 8; ++in)
#pragma unroll
            for (int j = 0; j < 4; ++j) s[in][j] = 0.f;

#pragma unroll
        for (int kk = 0; kk < 64; kk += 8) {
            const uint32_t a0 = __float_as_uint(sQ[(rA    ) * SQS + kk + tg    ]);
            const uint32_t a1 = __float_as_uint(sQ[(rA + 8) * SQS + kk + tg    ]);
            const uint32_t a2 = __float_as_uint(sQ[(rA    ) * SQS + kk + tg + 4]);
            const uint32_t a3 = __float_as_uint(sQ[(rA + 8) * SQS + kk + tg + 4]);
#pragma unroll
            for (int in = 0; in < 8; ++in) {
                const uint32_t b0 = __float_as_uint(sK[(in * 8 + g) * SQS + kk + tg    ]);
                const uint32_t b1 = __float_as_uint(sK[(in * 8 + g) * SQS + kk + tg + 4]);
                mma_m16n8k8(s[in], a0, a1, a2, a3, b0, b1);
            }
        }

        // causal mask on diagonal tiles
        if (jt >= 2 * qb) {
#pragma unroll
            for (int in = 0; in < 8; ++in) {
                const int cj = jt * 64 + in * 8 + tg * 2;
                if (cj     > qrA) s[in][0] = -1e30f;
                if (cj + 1 > qrA) s[in][1] = -1e30f;
                if (cj     > qrB) s[in][2] = -1e30f;
                if (cj + 1 > qrB) s[in][3] = -1e30f;
            }
        }

        // online softmax
        float rmA = -1e30f, rmB = -1e30f;
#pragma unroll
        for (int in = 0; in < 8; ++in) {
            rmA = fmaxf(rmA, fmaxf(s[in][0], s[in][1]));
            rmB = fmaxf(rmB, fmaxf(s[in][2], s[in][3]));
        }
        rmA = fmaxf(rmA, __shfl_xor_sync(0xffffffffu, rmA, 1));
        rmA = fmaxf(rmA, __shfl_xor_sync(0xffffffffu, rmA, 2));
        rmB = fmaxf(rmB, __shfl_xor_sync(0xffffffffu, rmB, 1));
        rmB = fmaxf(rmB, __shfl_xor_sync(0xffffffffu, rmB, 2));

        const float mA = fmaxf(mrow[0], rmA);
        const float mB = fmaxf(mrow[1], rmB);
        const float cA = __expf(mrow[0] - mA);
        const float cB = __expf(mrow[1] - mB);

        float rsA = 0.f, rsB = 0.f;
#pragma unroll
        for (int in = 0; in < 8; ++in) {
            const float p0 = __expf(s[in][0] - mA);
            const float p1 = __expf(s[in][1] - mA);
            const float p2 = __expf(s[in][2] - mB);
            const float p3 = __expf(s[in][3] - mB);
            rsA += p0 + p1;
            rsB += p2 + p3;
            const int col = in * 8 + tg * 2;
            *reinterpret_cast<float2*>(&sP[(rA    ) * SQS + col]) =
                make_float2(f2tf32f(p0), f2tf32f(p1));
            *reinterpret_cast<float2*>(&sP[(rA + 8) * SQS + col]) =
                make_float2(f2tf32f(p2), f2tf32f(p3));
        }
        rsA += __shfl_xor_sync(0xffffffffu, rsA, 1);
        rsA += __shfl_xor_sync(0xffffffffu, rsA, 2);
        rsB += __shfl_xor_sync(0xffffffffu, rsB, 1);
        rsB += __shfl_xor_sync(0xffffffffu, rsB, 2);

        lrow[0] = lrow[0] * cA + rsA;
        lrow[1] = lrow[1] * cB + rsB;
        mrow[0] = mA;
        mrow[1] = mB;

#pragma unroll
        for (int in = 0; in < 8; ++in) {
            o[in][0] *= cA;
            o[in][1] *= cA;
            o[in][2] *= cB;
            o[in][3] *= cB;
        }
        __syncwarp();

        // O += P @ V (sV swizzled -> conflict-free)
#pragma unroll
        for (int kk = 0; kk < 64; kk += 8) {
            const uint32_t a0 = __float_as_uint(sP[(rA    ) * SQS + kk + tg    ]);
            const uint32_t a1 = __float_as_uint(sP[(rA + 8) * SQS + kk + tg    ]);
            const uint32_t a2 = __float_as_uint(sP[(rA    ) * SQS + kk + tg + 4]);
            const uint32_t a3 = __float_as_uint(sP[(rA + 8) * SQS + kk + tg + 4]);
#pragma unroll
            for (int in = 0; in < 8; ++in) {
                const uint32_t b0 = __float_as_uint(sV[(kk + tg    ) * 64 + bcolV[in]]);
                const uint32_t b1 = __float_as_uint(sV[(kk + tg + 4) * 64 + bcolV[in]]);
                mma_m16n8k8(o[in], a0, a1, a2, a3, b0, b1);
            }
        }
    }

    const float invA = 1.f / lrow[0];
    const float invB = 1.f / lrow[1];
#pragma unroll
    for (int in = 0; in < 8; ++in) {
        const int col = in * 8 + tg * 2;
        *reinterpret_cast<float2*>(Y + base + (size_t)qrA * CDIM + col) =
            make_float2(o[in][0] * invA, o[in][1] * invA);
        *reinterpret_cast<float2*>(Y + base + (size_t)qrB * CDIM + col) =
            make_float2(o[in][2] * invB, o[in][3] * invB);
    }
}

// ---------------------------------------------------------------------------
// Cross-attention: 77 keys/head, padding mask. One thread per query row.
// ---------------------------------------------------------------------------
__global__ __launch_bounds__(128) void cross_attn_kernel(
    const float* __restrict__ Q, const float* __restrict__ Kc,
    const float* __restrict__ Vc, const int* __restrict__ pad,
    float* __restrict__ Yc)
{
    const int bh = blockIdx.y;
    const int b = bh >> 3;
    const int h = bh & 7;
    const int row0 = blockIdx.x * 128;
    const int tid = threadIdx.x;

    __shared__ float sQ[128 * 65];

    const size_t qbase = ((size_t)b * TLEN) * CDIM + h * DHEAD;
    for (int i = tid; i < 128 * 64; i += 128) {
        const int r = i >> 6, c = i & 63;
        sQ[r * 65 + c] = Q[qbase + (size_t)(row0 + r) * CDIM + c];
    }
    __syncthreads();

    const float* kb = Kc + ((size_t)b * MLEN) * CDIM + h * DHEAD;
    const float* vb = Vc + ((size_t)b * MLEN) * CDIM + h * DHEAD;
    const int* pb = pad + b * MLEN;
    const float* qrow = &sQ[tid * 65];

    float m = -1e30f;
    for (int j = 0; j < MLEN; ++j) {
        if (pb[j] == 0) continue;
        float dot = 0.f;
        const float* kr = kb + (size_t)j * CDIM;
#pragma unroll 16
        for (int d = 0; d < 64; ++d) dot = fmaf(qrow[d], kr[d], dot);
        m = fmaxf(m, dot * 0.125f);
    }

    float l = 0.f;
    float o[64];
#pragma unroll
    for (int d = 0; d < 64; ++d) o[d] = 0.f;

    for (int j = 0; j < MLEN; ++j) {
        if (pb[j] == 0) continue;
        float dot = 0.f;
        const float* kr = kb + (size_t)j * CDIM;
#pragma unroll 16
        for (int d = 0; d < 64; ++d) dot = fmaf(qrow[d], kr[d], dot);
        const float p = __expf(dot * 0.125f - m);
        l += p;
        const float* vr = vb + (size_t)j * CDIM;
#pragma unroll 16
        for (int d = 0; d < 64; ++d) o[d] = fmaf(p, vr[d], o[d]);
    }

    const float inv = (l > 0.f) ? (1.f / l) : 0.f;
    float* yout = Yc + qbase + (size_t)(row0 + tid) * CDIM;
#pragma unroll 16
    for (int d = 0; d < 64; ++d) yout[d] = o[d] * inv;
}

// ---------------------------------------------------------------------------
// fused = sigmoid(g1) * yc + sigmoid(g2) * y
// ---------------------------------------------------------------------------
__device__ __forceinline__ float sigf(float x) {
    return 1.f / (1.f + __expf(-x));
}

__global__ __launch_bounds__(256) void gate_fuse_kernel(
    const float* __restrict__ g1, const float* __restrict__ g2,
    const float* __restrict__ y, const float* __restrict__ yc,
    float* __restrict__ out)
{
    const int i = blockIdx.x * blockDim.x + threadIdx.x;
    const float4 a = reinterpret_cast<const float4*>(g1)[i];
    const float4 bg = reinterpret_cast<const float4*>(g2)[i];
    const float4 yv = reinterpret_cast<const float4*>(y)[i];
    const float4 yw = reinterpret_cast<const float4*>(yc)[i];
    float4 o;
    o.x = sigf(a.x) * yw.x + sigf(bg.x) * yv.x;
    o.y = sigf(a.y) * yw.y + sigf(bg.y) * yv.y;
    o.z = sigf(a.z) * yw.z + sigf(bg.z) * yv.z;
    o.w = sigf(a.w) * yw.w + sigf(bg.w) * yv.w;
    reinterpret_cast<float4*>(out)[i] = o;
}

// ---------------------------------------------------------------------------
// Launch
// ---------------------------------------------------------------------------
extern "C" void kernel_launch(void* const* d_in, const int* in_sizes, int n_in,
                              void* d_out, int out_size)
{
    const float* x  = (const float*)d_in[0];
    const float* c  = (const float*)d_in[1];
    const int* pad  = (const int*)d_in[3];
    const float* Wq = (const float*)d_in[4];
    const float* bq = (const float*)d_in[5];
    const float* Wk = (const float*)d_in[6];
    const float* bk = (const float*)d_in[7];
    const float* Wv = (const float*)d_in[8];
    const float* bv = (const float*)d_in[9];
    const float* Wkc = (const float*)d_in[10];
    const float* bkc = (const float*)d_in[11];
    const float* Wvc = (const float*)d_in[12];
    const float* bvc = (const float*)d_in[13];
    const float* Wg1 = (const float*)d_in[14];
    const float* bg1 = (const float*)d_in[15];
    const float* Wg2 = (const float*)d_in[16];
    const float* bg2 = (const float*)d_in[17];
    const float* Wp = (const float*)d_in[18];
    const float* bp = (const float*)d_in[19];
    float* out = (float*)d_out;

    float* S = nullptr;
    cudaGetSymbolAddress((void**)&S, g_scratch);
    float* Qb  = S + 0ULL * NBIG;
    float* Kb  = S + 1ULL * NBIG;
    float* Vb  = S + 2ULL * NBIG;
    float* Yb  = S + 3ULL * NBIG;
    float* YCb = S + 4ULL * NBIG;
    float* G1b = S + 5ULL * NBIG;
    float* G2b = S + 6ULL * NBIG;
    float* Fb  = S + 7ULL * NBIG;
    float* KCb = S + 8ULL * NBIG;
    float* VCb = S + 8ULL * NBIG + NSMALL;

    const int SMEM_SA = (256 * SQS + 64 * SQS + 64 * 64) * (int)sizeof(float); // 113664
    cudaFuncSetAttribute(self_attn_mma,
                         cudaFuncAttributeMaxDynamicSharedMemorySize, SMEM_SA);

    proj_kernel<<<400, 256>>>(x, c, Wq, bq, Wk, bk, Wv, bv,
                              Wkc, bkc, Wvc, bvc, Qb, Kb, Vb, KCb, VCb);

    self_attn_mma<<<dim3(TLEN / 128, BATCH * HEADS), 256, SMEM_SA>>>(Qb, Kb, Vb, Yb);
    cross_attn_kernel<<<dim3(TLEN / 128, BATCH * HEADS), 128>>>(Qb, KCb, VCb, pad, YCb);

    gates_kernel<<<256, 256>>>(Yb, YCb, Wg1, bg1, Wg2, bg2, G1b, G2b);
    gate_fuse_kernel<<<NBIG / 4 / 256, 256>>>(G1b, G2b, Yb, YCb, Fb);
    final_gemm_kernel<<<128, 256>>>(Fb, Wp, bp, out);
}

// round 5
// speedup vs baseline: 3.4618x; 3.3029x over previous
#include <cuda_runtime.h>
#include <cuda_fp16.h>
#include <math.h>
#include <stdint.h>

#define BATCH 2
#define TLEN 2048
#define MLEN 77
#define CDIM 512
#define HEADS 8
#define BT 4096
#define NBIG 2097152
#define NSMALL 78848
#define MSMALL 154
#define WTSZ 262144
#define QSCALE 0.18033688011112042f   // 0.125 * log2(e)
#define NEGB (-30000.0f)

// fp16 scratch: XH,Q,K,V,Y,YC,G1,G2,F (9*NBIG), CH,KC,VC (3*NSMALL), WT[8]
__device__ __half g_h[9ULL * NBIG + 3ULL * NSMALL + 8ULL * WTSZ];

// ---------------------------------------------------------------------------
// helpers
// ---------------------------------------------------------------------------
__device__ __forceinline__ uint32_t smem_u32(const void* p) {
    return (uint32_t)__cvta_generic_to_shared(p);
}
__device__ __forceinline__ void ldsm_x4(uint32_t& r0, uint32_t& r1,
                                        uint32_t& r2, uint32_t& r3, uint32_t a) {
    asm volatile("ldmatrix.sync.aligned.m8n8.x4.shared.b16 {%0,%1,%2,%3}, [%4];"
                 : "=r"(r0), "=r"(r1), "=r"(r2), "=r"(r3) : "r"(a));
}
__device__ __forceinline__ void ldsm_x4_t(uint32_t& r0, uint32_t& r1,
                                          uint32_t& r2, uint32_t& r3, uint32_t a) {
    asm volatile("ldmatrix.sync.aligned.m8n8.x4.trans.shared.b16 {%0,%1,%2,%3}, [%4];"
                 : "=r"(r0), "=r"(r1), "=r"(r2), "=r"(r3) : "r"(a));
}
__device__ __forceinline__ void mma16816(float (&d)[4],
    uint32_t a0, uint32_t a1, uint32_t a2, uint32_t a3, uint32_t b0, uint32_t b1) {
    asm volatile(
        "mma.sync.aligned.m16n8k16.row.col.f32.f16.f16.f32 "
        "{%0,%1,%2,%3}, {%4,%5,%6,%7}, {%8,%9}, {%0,%1,%2,%3};\n"
        : "+f"(d[0]), "+f"(d[1]), "+f"(d[2]), "+f"(d[3])
        : "r"(a0), "r"(a1), "r"(a2), "r"(a3), "r"(b0), "r"(b1));
}
__device__ __forceinline__ float ex2(float x) {
    float r;
    asm("ex2.approx.ftz.f32 %0, %1;" : "=f"(r) : "f"(x));
    return r;
}

// ---------------------------------------------------------------------------
// prep: x, c -> fp16
// ---------------------------------------------------------------------------
__global__ __launch_bounds__(256) void convert_xc_kernel(
    const float* __restrict__ x, const float* __restrict__ c,
    __half* __restrict__ xh, __half* __restrict__ ch)
{
    const int i = blockIdx.x * 256 + threadIdx.x;
    const float* src;
    __half* dst;
    int k;
    if (i < NBIG / 8) { src = x; dst = xh; k = i; }
    else if (i < (NBIG + NSMALL) / 8) { src = c; dst = ch; k = i - NBIG / 8; }
    else return;
    const float4 f0 = reinterpret_cast<const float4*>(src)[k * 2];
    const float4 f1 = reinterpret_cast<const float4*>(src)[k * 2 + 1];
    __half2 h[4];
    h[0] = __floats2half2_rn(f0.x, f0.y);
    h[1] = __floats2half2_rn(f0.z, f0.w);
    h[2] = __floats2half2_rn(f1.x, f1.y);
    h[3] = __floats2half2_rn(f1.z, f1.w);
    reinterpret_cast<uint4*>(dst)[k] = *reinterpret_cast<uint4*>(h);
}

// prep: W[k][n] fp32 -> Wt[n][k] fp16 (8 matrices)
__global__ void transpose_w_kernel(
    const float* __restrict__ W0, const float* __restrict__ W1,
    const float* __restrict__ W2, const float* __restrict__ W3,
    const float* __restrict__ W4, const float* __restrict__ W5,
    const float* __restrict__ W6, const float* __restrict__ W7,
    __half* __restrict__ Wt)
{
    __shared__ __half t[32][33];
    const int z = blockIdx.z;
    const float* src = (z == 0) ? W0 : (z == 1) ? W1 : (z == 2) ? W2 : (z == 3) ? W3
                     : (z == 4) ? W4 : (z == 5) ? W5 : (z == 6) ? W6 : W7;
    __half* dst = Wt + (size_t)z * WTSZ;
    const int tx = threadIdx.x, ty = threadIdx.y;
    const int k0 = blockIdx.y * 32, n0 = blockIdx.x * 32;
#pragma unroll
    for (int i = 0; i < 4; ++i)
        t[ty + i * 8][tx] = __float2half_rn(src[(size_t)(k0 + ty + i * 8) * 512 + n0 + tx]);
    __syncthreads();
#pragma unroll
    for (int i = 0; i < 4; ++i)
        dst[(size_t)(n0 + ty + i * 8) * 512 + k0 + tx] = t[tx][ty + i * 8];
}

// ---------------------------------------------------------------------------
// fp16 GEMM core: out[m0:+128, n0:+128] = A[.,512] @ Wt^T + bias (opt *oscale)
// A fp16 row-major, Wt fp16 [n][k]. 256 thr, 8 warps (4x2), BK=32, dbuf.
// ---------------------------------------------------------------------------
__device__ __forceinline__ void gemm_core(
    const __half* __restrict__ A, const __half* __restrict__ Wt,
    const float* __restrict__ bias,
    __half* __restrict__ outh, float* __restrict__ outf, float oscale,
    int Mrows, int m0, int n0)
{
    __shared__ __half sA[2][128][40];
    __shared__ __half sB[2][128][40];

    const int tid = threadIdx.x;
    const int lane = tid & 31;
    const int wid = tid >> 5;
    const int wm = (wid >> 1) * 32;
    const int wn = (wid & 1) * 64;
    const int g = lane >> 2;
    const int tg = lane & 3;

    const int ar = tid >> 1;
    const int ak = (tid & 1) * 16;
    const bool aok = (m0 + ar) < Mrows;
    const __half* aptr = A + (size_t)(m0 + ar) * 512 + ak;
    const __half* bptr = Wt + (size_t)(n0 + ar) * 512 + ak;

    const int arow = wm + (lane & 15);
    const int acol = (lane >> 4) * 8;
    const int brow = wn + ((lane >> 3) & 1) * 8 + (lane & 7);
    const int bcol = (lane >> 4) * 8;

    float acc[2][8][4];
#pragma unroll
    for (int im = 0; im < 2; ++im)
#pragma unroll
        for (int in = 0; in < 8; ++in)
#pragma unroll
            for (int j = 0; j < 4; ++j) acc[im][in][j] = 0.f;

    uint4 ra0, ra1, rb0, rb1;
    const uint4 z4 = make_uint4(0, 0, 0, 0);

    auto load_stage = [&](int k0) {
        ra0 = aok ? *reinterpret_cast<const uint4*>(aptr + k0) : z4;
        ra1 = aok ? *reinterpret_cast<const uint4*>(aptr + k0 + 8) : z4;
        rb0 = *reinterpret_cast<const uint4*>(bptr + k0);
        rb1 = *reinterpret_cast<const uint4*>(bptr + k0 + 8);
    };
    auto store_stage = [&](int buf) {
        *reinterpret_cast<uint4*>(&sA[buf][ar][ak]) = ra0;
        *reinterpret_cast<uint4*>(&sA[buf][ar][ak + 8]) = ra1;
        *reinterpret_cast<uint4*>(&sB[buf][ar][ak]) = rb0;
        *reinterpret_cast<uint4*>(&sB[buf][ar][ak + 8]) = rb1;
    };

    load_stage(0);
    store_stage(0);
    __syncthreads();

#pragma unroll 1
    for (int it = 0; it < 16; ++it) {
        const int buf = it & 1;
        if (it < 15) load_stage((it + 1) * 32);

#pragma unroll
        for (int kc = 0; kc < 32; kc += 16) {
            uint32_t a[2][4];
#pragma unroll
            for (int im = 0; im < 2; ++im)
                ldsm_x4(a[im][0], a[im][1], a[im][2], a[im][3],
                        smem_u32(&sA[buf][arow + im * 16][acol + kc]));
#pragma unroll
            for (int nq = 0; nq < 4; ++nq) {
                uint32_t b0, b1, b2, b3;
                ldsm_x4(b0, b1, b2, b3,
                        smem_u32(&sB[buf][brow + nq * 16][bcol + kc]));
#pragma unroll
                for (int im = 0; im < 2; ++im) {
                    mma16816(acc[im][2 * nq],     a[im][0], a[im][1], a[im][2], a[im][3], b0, b2);
                    mma16816(acc[im][2 * nq + 1], a[im][0], a[im][1], a[im][2], a[im][3], b1, b3);
                }
            }
        }
        if (it < 15) {
            store_stage(1 - buf);
            __syncthreads();
        }
    }

#pragma unroll
    for (int in = 0; in < 8; ++in) {
        const int col = n0 + wn + in * 8 + tg * 2;
        const float2 bb = *reinterpret_cast<const float2*>(bias + col);
#pragma unroll
        for (int im = 0; im < 2; ++im) {
            const int r0 = m0 + wm + im * 16 + g;
            const int r1 = r0 + 8;
            if (r0 < Mrows) {
                const float v0 = (acc[im][in][0] + bb.x) * oscale;
                const float v1 = (acc[im][in][1] + bb.y) * oscale;
                if (outh)
                    *reinterpret_cast<__half2*>(outh + (size_t)r0 * 512 + col) =
                        __floats2half2_rn(v0, v1);
                else
                    *reinterpret_cast<float2*>(outf + (size_t)r0 * 512 + col) =
                        make_float2(v0, v1);
            }
            if (r1 < Mrows) {
                const float v2 = (acc[im][in][2] + bb.x) * oscale;
                const float v3 = (acc[im][in][3] + bb.y) * oscale;
                if (outh)
                    *reinterpret_cast<__half2*>(outh + (size_t)r1 * 512 + col) =
                        __floats2half2_rn(v2, v3);
                else
                    *reinterpret_cast<float2*>(outf + (size_t)r1 * 512 + col) =
                        make_float2(v2, v3);
            }
        }
    }
}

// projections: Q(pre-scaled),K,V (3x128) + KC,VC (2x8) = 400 blocks
__global__ __launch_bounds__(256) void proj_kernel(
    const __half* __restrict__ xh, const __half* __restrict__ ch,
    const __half* __restrict__ Wt,
    const float* __restrict__ bq, const float* __restrict__ bk,
    const float* __restrict__ bv, const float* __restrict__ bkc,
    const float* __restrict__ bvc,
    __half* __restrict__ Qh, __half* __restrict__ Kh, __half* __restrict__ Vh,
    __half* __restrict__ KCh, __half* __restrict__ VCh)
{
    const int bid = blockIdx.x;
    const __half *A, *W;
    const float* bias;
    __half* out;
    float oscale = 1.0f;
    int Mrows, m0, n0;
    if (bid < 384) {
        const int t = bid / 128, l = bid % 128;
        m0 = (l >> 2) * 128;
        n0 = (l & 3) * 128;
        A = xh; Mrows = BT;
        W = Wt + (size_t)t * WTSZ;
        bias = (t == 0) ? bq : ((t == 1) ? bk : bv);
        out = (t == 0) ? Qh : ((t == 1) ? Kh : Vh);
        if (t == 0) oscale = QSCALE;
    } else {
        const int r = bid - 384;
        const int t = r / 8, l = r % 8;
        m0 = (l >> 2) * 128;
        n0 = (l & 3) * 128;
        A = ch; Mrows = MSMALL;
        W = Wt + (size_t)(3 + t) * WTSZ;
        bias = t ? bvc : bkc;
        out = t ? VCh : KCh;
    }
    gemm_core(A, W, bias, out, nullptr, oscale, Mrows, m0, n0);
}

__global__ __launch_bounds__(256) void gates_kernel(
    const __half* __restrict__ Yh, const __half* __restrict__ YCh,
    const __half* __restrict__ Wt,
    const float* __restrict__ bg1, const float* __restrict__ bg2,
    __half* __restrict__ G1, __half* __restrict__ G2)
{
    const int bid = blockIdx.x;
    const int t = bid >> 7;
    const int l = bid & 127;
    gemm_core(t ? YCh : Yh, Wt + (size_t)(5 + t) * WTSZ, t ? bg2 : bg1,
              t ? G2 : G1, nullptr, 1.0f, BT, (l >> 2) * 128, (l & 3) * 128);
}

__global__ __launch_bounds__(256) void final_gemm_kernel(
    const __half* __restrict__ F, const __half* __restrict__ Wt,
    const float* __restrict__ bp, float* __restrict__ out)
{
    const int l = blockIdx.x;
    gemm_core(F, Wt + 7ULL * WTSZ, bp, nullptr, out, 1.0f, BT,
              (l >> 2) * 128, (l & 3) * 128);
}

// ---------------------------------------------------------------------------
// Flash self-attention (causal), fp16 mma + ldmatrix, base-2 softmax.
// 128 q/block, 8 warps (16 rows each), 64-key tiles. grid (16, B*H).
// ---------------------------------------------------------------------------
#define SAS 72

__global__ __launch_bounds__(256) void self_attn_mma(
    const __half* __restrict__ Q, const __half* __restrict__ K,
    const __half* __restrict__ V, __half* __restrict__ Y)
{
    extern __shared__ __half smh[];
    __half* sQ = smh;                 // [128][72]
    __half* sP = sQ + 128 * SAS;      // [128][72]
    __half* sK = sP + 128 * SAS;      // [64][72]
    __half* sV = sK + 64 * SAS;       // [64][72]

    const int qb = (int)gridDim.x - 1 - (int)blockIdx.x;
    const int bh = blockIdx.y;
    const int b = bh >> 3;
    const int h = bh & 7;
    const int tid = threadIdx.x;
    const int lane = tid & 31;
    const int wid = tid >> 5;
    const int g = lane >> 2;
    const int tg = lane & 3;
    const int wm = wid * 16;

    const size_t base = ((size_t)b * TLEN) * CDIM + h * 64;

    // stage Q (128 x 64 halves)
    {
        const int r = tid >> 1, cb = (tid & 1) * 32;
        const uint4* src = reinterpret_cast<const uint4*>(
            Q + base + (size_t)(qb * 128 + r) * CDIM + cb);
        uint4* dst = reinterpret_cast<uint4*>(&sQ[r * SAS + cb]);
        dst[0] = src[0]; dst[1] = src[1]; dst[2] = src[2]; dst[3] = src[3];
    }

    const int arow = wm + (lane & 15);
    const int acol = (lane >> 4) * 8;
    const int brow = ((lane >> 3) & 1) * 8 + (lane & 7);   // K/P-as-B rows
    const int bcol = (lane >> 4) * 8;
    const int vrow = (lane & 7) + ((lane >> 4) & 1) * 8;   // V trans rows
    const int vcol = ((lane >> 3) & 1) * 8;
    const int kvr = tid >> 2, kvc = (tid & 3) * 16;

    float o[8][4];
#pragma unroll
    for (int in = 0; in < 8; ++in)
#pragma unroll
        for (int j = 0; j < 4; ++j) o[in][j] = 0.f;
    float mrow[2] = {NEGB, NEGB};
    float lrow[2] = {0.f, 0.f};

    const int rA = wm + g;
    const int qrA = qb * 128 + rA;
    const int qrB = qrA + 8;

    const int nIter = 2 * (qb + 1);
    for (int jt = 0; jt < nIter; ++jt) {
        __syncthreads();
        {
            const size_t gofs = base + (size_t)(jt * 64 + kvr) * CDIM + kvc;
            const uint4* ks = reinterpret_cast<const uint4*>(K + gofs);
            const uint4* vs = reinterpret_cast<const uint4*>(V + gofs);
            uint4* kd = reinterpret_cast<uint4*>(&sK[kvr * SAS + kvc]);
            uint4* vd = reinterpret_cast<uint4*>(&sV[kvr * SAS + kvc]);
            kd[0] = ks[0]; kd[1] = ks[1];
            vd[0] = vs[0]; vd[1] = vs[1];
        }
        __syncthreads();

        // S = Q @ K^T (Q pre-scaled by 0.125*log2e)
        float s[8][4];
#pragma unroll
        for (int in = 0; in < 8; ++in)
#pragma unroll
            for (int j = 0; j < 4; ++j) s[in][j] = 0.f;

#pragma unroll
        for (int kc = 0; kc < 64; kc += 16) {
            uint32_t a0, a1, a2, a3;
            ldsm_x4(a0, a1, a2, a3, smem_u32(&sQ[arow * SAS + acol + kc]));
#pragma unroll
            for (int nq = 0; nq < 4; ++nq) {
                uint32_t b0, b1, b2, b3;
                ldsm_x4(b0, b1, b2, b3,
                        smem_u32(&sK[(nq * 16 + brow) * SAS + bcol + kc]));
                mma16816(s[2 * nq],     a0, a1, a2, a3, b0, b2);
                mma16816(s[2 * nq + 1], a0, a1, a2, a3, b1, b3);
            }
        }

        if (jt >= 2 * qb) {
#pragma unroll
            for (int in = 0; in < 8; ++in) {
                const int cj = jt * 64 + in * 8 + tg * 2;
                if (cj     > qrA) s[in][0] = NEGB;
                if (cj + 1 > qrA) s[in][1] = NEGB;
                if (cj     > qrB) s[in][2] = NEGB;
                if (cj + 1 > qrB) s[in][3] = NEGB;
            }
        }

        float rmA = NEGB, rmB = NEGB;
#pragma unroll
        for (int in = 0; in < 8; ++in) {
            rmA = fmaxf(rmA, fmaxf(s[in][0], s[in][1]));
            rmB = fmaxf(rmB, fmaxf(s[in][2], s[in][3]));
        }
        rmA = fmaxf(rmA, __shfl_xor_sync(0xffffffffu, rmA, 1));
        rmA = fmaxf(rmA, __shfl_xor_sync(0xffffffffu, rmA, 2));
        rmB = fmaxf(rmB, __shfl_xor_sync(0xffffffffu, rmB, 1));
        rmB = fmaxf(rmB, __shfl_xor_sync(0xffffffffu, rmB, 2));

        const float mA = fmaxf(mrow[0], rmA);
        const float mB = fmaxf(mrow[1], rmB);
        const float cA = ex2(mrow[0] - mA);
        const float cB = ex2(mrow[1] - mB);

        float rsA = 0.f, rsB = 0.f;
#pragma unroll
        for (int in = 0; in < 8; ++in) {
            const float p0 = ex2(s[in][0] - mA);
            const float p1 = ex2(s[in][1] - mA);
            const float p2 = ex2(s[in][2] - mB);
            const float p3 = ex2(s[in][3] - mB);
            rsA += p0 + p1;
            rsB += p2 + p3;
            const int col = in * 8 + tg * 2;
            *reinterpret_cast<__half2*>(&sP[rA * SAS + col]) = __floats2half2_rn(p0, p1);
            *reinterpret_cast<__half2*>(&sP[(rA + 8) * SAS + col]) = __floats2half2_rn(p2, p3);
        }
        rsA += __shfl_xor_sync(0xffffffffu, rsA, 1);
        rsA += __shfl_xor_sync(0xffffffffu, rsA, 2);
        rsB += __shfl_xor_sync(0xffffffffu, rsB, 1);
        rsB += __shfl_xor_sync(0xffffffffu, rsB, 2);

        lrow[0] = lrow[0] * cA + rsA;
        lrow[1] = lrow[1] * cB + rsB;
        mrow[0] = mA;
        mrow[1] = mB;

#pragma unroll
        for (int in = 0; in < 8; ++in) {
            o[in][0] *= cA; o[in][1] *= cA;
            o[in][2] *= cB; o[in][3] *= cB;
        }
        __syncwarp();

        // O += P @ V
#pragma unroll
        for (int kc = 0; kc < 64; kc += 16) {
            uint32_t a0, a1, a2, a3;
            ldsm_x4(a0, a1, a2, a3, smem_u32(&sP[arow * SAS + acol + kc]));
#pragma unroll
            for (int dq = 0; dq < 4; ++dq) {
                uint32_t b0, b1, b2, b3;
                ldsm_x4_t(b0, b1, b2, b3,
                          smem_u32(&sV[(kc + vrow) * SAS + dq * 16 + vcol]));
                mma16816(o[2 * dq],     a0, a1, a2, a3, b0, b2);
                mma16816(o[2 * dq + 1], a0, a1, a2, a3, b1, b3);
            }
        }
    }

    const float invA = 1.f / lrow[0];
    const float invB = 1.f / lrow[1];
#pragma unroll
    for (int in = 0; in < 8; ++in) {
        const int col = in * 8 + tg * 2;
        *reinterpret_cast<__half2*>(Y + base + (size_t)qrA * CDIM + col) =
            __floats2half2_rn(o[in][0] * invA, o[in][1] * invA);
        *reinterpret_cast<__half2*>(Y + base + (size_t)qrB * CDIM + col) =
            __floats2half2_rn(o[in][2] * invB, o[in][3] * invB);
    }
}

// ---------------------------------------------------------------------------
// Cross-attention via mma: 128 q/block, 80 padded keys, padding mask.
// grid (16, B*H), 256 threads. Q pre-scaled; base-2 softmax (single pass).
// ---------------------------------------------------------------------------
#define CPS 88

__global__ __launch_bounds__(256) void cross_attn_mma(
    const __half* __restrict__ Q, const __half* __restrict__ Kc,
    const __half* __restrict__ Vc, const int* __restrict__ pad,
    __half* __restrict__ Yc)
{
    extern __shared__ __half smh[];
    __half* sQ = smh;                 // [128][72]
    __half* sP = sQ + 128 * SAS;      // [128][88]
    __half* sK = sP + 128 * CPS;      // [80][72]
    __half* sV = sK + 80 * SAS;       // [80][72]
    int* sF = (int*)(sV + 80 * SAS);  // [80]

    const int bh = blockIdx.y;
    const int b = bh >> 3;
    const int h = bh & 7;
    const int qb = blockIdx.x;
    const int tid = threadIdx.x;
    const int lane = tid & 31;
    const int wid = tid >> 5;
    const int g = lane >> 2;
    const int tg = lane & 3;
    const int wm = wid * 16;

    const size_t qbase = ((size_t)b * TLEN) * CDIM + h * 64;
    const size_t kbase = ((size_t)b * MLEN) * CDIM + h * 64;

    // stage Q
    {
        const int r = tid >> 1, cb = (tid & 1) * 32;
        const uint4* src = reinterpret_cast<const uint4*>(
            Q + qbase + (size_t)(qb * 128 + r) * CDIM + cb);
        uint4* dst = reinterpret_cast<uint4*>(&sQ[r * SAS + cb]);
        dst[0] = src[0]; dst[1] = src[1]; dst[2] = src[2]; dst[3] = src[3];
    }
    // stage K/V (77 rows + 3 zero rows)
    {
        const int r = tid >> 1, cb = (tid & 1) * 32;
        if (r < 80) {
            uint4 kv0, kv1, kv2, kv3, vv0, vv1, vv2, vv3;
            if (r < MLEN) {
                const uint4* ks = reinterpret_cast<const uint4*>(Kc + kbase + (size_t)r * CDIM + cb);
                const uint4* vs = reinterpret_cast<const uint4*>(Vc + kbase + (size_t)r * CDIM + cb);
                kv0 = ks[0]; kv1 = ks[1]; kv2 = ks[2]; kv3 = ks[3];
                vv0 = vs[0]; vv1 = vs[1]; vv2 = vs[2]; vv3 = vs[3];
            } else {
                kv0 = kv1 = kv2 = kv3 = make_uint4(0, 0, 0, 0);
                vv0 = vv1 = vv2 = vv3 = kv0;
            }
            uint4* kd = reinterpret_cast<uint4*>(&sK[r * SAS + cb]);
            uint4* vd = reinterpret_cast<uint4*>(&sV[r * SAS + cb]);
            kd[0] = kv0; kd[1] = kv1; kd[2] = kv2; kd[3] = kv3;
            vd[0] = vv0; vd[1] = vv1; vd[2] = vv2; vd[3] = vv3;
        }
    }
    if (tid < 80) sF[tid] = (tid < MLEN) ? pad[b * MLEN + tid] : 0;
    __syncthreads();

    const int arow = wm + (lane & 15);
    const int acol = (lane >> 4) * 8;
    const int brow = ((lane >> 3) & 1) * 8 + (lane & 7);
    const int bcol = (lane >> 4) * 8;
    const int vrow = (lane & 7) + ((lane >> 4) & 1) * 8;
    const int vcol = ((lane >> 3) & 1) * 8;

    // S = Q @ K^T : 16 x 80 per warp
    float s[10][4];
#pragma unroll
    for (int in = 0; in < 10; ++in)
#pragma unroll
        for (int j = 0; j < 4; ++j) s[in][j] = 0.f;

#pragma unroll
    for (int kc = 0; kc < 64; kc += 16) {
        uint32_t a0, a1, a2, a3;
        ldsm_x4(a0, a1, a2, a3, smem_u32(&sQ[arow * SAS + acol + kc]));
#pragma unroll
        for (int nq = 0; nq < 5; ++nq) {
            uint32_t b0, b1, b2, b3;
            ldsm_x4(b0, b1, b2, b3,
                    smem_u32(&sK[(nq * 16 + brow) * SAS + bcol + kc]));
            mma16816(s[2 * nq],     a0, a1, a2, a3, b0, b2);
            mma16816(s[2 * nq + 1], a0, a1, a2, a3, b1, b3);
        }
    }

    // padding mask
#pragma unroll
    for (int in = 0; in < 10; ++in) {
        const int cj = in * 8 + tg * 2;
        if (sF[cj] == 0)     { s[in][0] = NEGB; s[in][2] = NEGB; }
        if (sF[cj + 1] == 0) { s[in][1] = NEGB; s[in][3] = NEGB; }
    }

    // softmax (single pass)
    float rmA = NEGB, rmB = NEGB;
#pragma unroll
    for (int in = 0; in < 10; ++in) {
        rmA = fmaxf(rmA, fmaxf(s[in][0], s[in][1]));
        rmB = fmaxf(rmB, fmaxf(s[in][2], s[in][3]));
    }
    rmA = fmaxf(rmA, __shfl_xor_sync(0xffffffffu, rmA, 1));
    rmA = fmaxf(rmA, __shfl_xor_sync(0xffffffffu, rmA, 2));
    rmB = fmaxf(rmB, __shfl_xor_sync(0xffffffffu, rmB, 1));
    rmB = fmaxf(rmB, __shfl_xor_sync(0xffffffffu, rmB, 2));

    const int rA = wm + g;
    float rsA = 0.f, rsB = 0.f;
#pragma unroll
    for (int in = 0; in < 10; ++in) {
        const float p0 = ex2(s[in][0] - rmA);
        const float p1 = ex2(s[in][1] - rmA);
        const float p2 = ex2(s[in][2] - rmB);
        const float p3 = ex2(s[in][3] - rmB);
        rsA += p0 + p1;
        rsB += p2 + p3;
        const int col = in * 8 + tg * 2;
        *reinterpret_cast<__half2*>(&sP[rA * CPS + col]) = __floats2half2_rn(p0, p1);
        *reinterpret_cast<__half2*>(&sP[(rA + 8) * CPS + col]) = __floats2half2_rn(p2, p3);
    }
    rsA += __shfl_xor_sync(0xffffffffu, rsA, 1);
    rsA += __shfl_xor_sync(0xffffffffu, rsA, 2);
    rsB += __shfl_xor_sync(0xffffffffu, rsB, 1);
    rsB += __shfl_xor_sync(0xffffffffu, rsB, 2);
    __syncwarp();

    // O = P @ V : k = 80
    float o[8][4];
#pragma unroll
    for (int in = 0; in < 8; ++in)
#pragma unroll
        for (int j = 0; j < 4; ++j) o[in][j] = 0.f;

#pragma unroll
    for (int kc = 0; kc < 80; kc += 16) {
        uint32_t a0, a1, a2, a3;
        ldsm_x4(a0, a1, a2, a3, smem_u32(&sP[arow * CPS + acol + kc]));
#pragma unroll
        for (int dq = 0; dq < 4; ++dq) {
            uint32_t b0, b1, b2, b3;
            ldsm_x4_t(b0, b1, b2, b3,
                      smem_u32(&sV[(kc + vrow) * SAS + dq * 16 + vcol]));
            mma16816(o[2 * dq],     a0, a1, a2, a3, b0, b2);
            mma16816(o[2 * dq + 1], a0, a1, a2, a3, b1, b3);
        }
    }

    const float invA = (rsA > 0.f) ? (1.f / rsA) : 0.f;
    const float invB = (rsB > 0.f) ? (1.f / rsB) : 0.f;
    const int qrA = qb * 128 + rA;
    const int qrB = qrA + 8;
#pragma unroll
    for (int in = 0; in < 8; ++in) {
        const int col = in * 8 + tg * 2;
        *reinterpret_cast<__half2*>(Yc + qbase + (size_t)qrA * CDIM + col) =
            __floats2half2_rn(o[in][0] * invA, o[in][1] * invA);
        *reinterpret_cast<__half2*>(Yc + qbase + (size_t)qrB * CDIM + col) =
            __floats2half2_rn(o[in][2] * invB, o[in][3] * invB);
    }
}

// ---------------------------------------------------------------------------
// fused = sigmoid(g1) * yc + sigmoid(g2) * y  (fp16 in/out)
// ---------------------------------------------------------------------------
__device__ __forceinline__ float sigf(float x) {
    return 1.f / (1.f + __expf(-x));
}

__global__ __launch_bounds__(256) void gate_fuse_kernel(
    const __half* __restrict__ g1, const __half* __restrict__ g2,
    const __half* __restrict__ y, const __half* __restrict__ yc,
    __half* __restrict__ f)
{
    const int i = blockIdx.x * 256 + threadIdx.x;  // uint4 = 8 halves
    const uint4 ua = reinterpret_cast<const uint4*>(g1)[i];
    const uint4 ub = reinterpret_cast<const uint4*>(g2)[i];
    const uint4 uy = reinterpret_cast<const uint4*>(y)[i];
    const uint4 uc = reinterpret_cast<const uint4*>(yc)[i];
    const __half2* ha = reinterpret_cast<const __half2*>(&ua);
    const __half2* hb = reinterpret_cast<const __half2*>(&ub);
    const __half2* hy = reinterpret_cast<const __half2*>(&uy);
    const __half2* hc = reinterpret_cast<const __half2*>(&uc);
    __half2 ho[4];
#pragma unroll
    for (int k = 0; k < 4; ++k) {
        const float2 a = __half22float2(ha[k]);
        const float2 bg = __half22float2(hb[k]);
        const float2 yv = __half22float2(hy[k]);
        const float2 yw = __half22float2(hc[k]);
        ho[k] = __floats2half2_rn(sigf(a.x) * yw.x + sigf(bg.x) * yv.x,
                                  sigf(a.y) * yw.y + sigf(bg.y) * yv.y);
    }
    reinterpret_cast<uint4*>(f)[i] = *reinterpret_cast<uint4*>(ho);
}

// ---------------------------------------------------------------------------
// Launch
// ---------------------------------------------------------------------------
extern "C" void kernel_launch(void* const* d_in, const int* in_sizes, int n_in,
                              void* d_out, int out_size)
{
    const float* x  = (const float*)d_in[0];
    const float* c  = (const float*)d_in[1];
    const int* pad  = (const int*)d_in[3];
    const float* Wq = (const float*)d_in[4];
    const float* bq = (const float*)d_in[5];
    const float* Wk = (const float*)d_in[6];
    const float* bk = (const float*)d_in[7];
    const float* Wv = (const float*)d_in[8];
    const float* bv = (const float*)d_in[9];
    const float* Wkc = (const float*)d_in[10];
    const float* bkc = (const float*)d_in[11];
    const float* Wvc = (const float*)d_in[12];
    const float* bvc = (const float*)d_in[13];
    const float* Wg1 = (const float*)d_in[14];
    const float* bg1 = (const float*)d_in[15];
    const float* Wg2 = (const float*)d_in[16];
    const float* bg2 = (const float*)d_in[17];
    const float* Wp = (const float*)d_in[18];
    const float* bp = (const float*)d_in[19];
    float* out = (float*)d_out;

    __half* H = nullptr;
    cudaGetSymbolAddress((void**)&H, g_h);
    __half* XH  = H + 0ULL * NBIG;
    __half* Qh  = H + 1ULL * NBIG;
    __half* Kh  = H + 2ULL * NBIG;
    __half* Vh  = H + 3ULL * NBIG;
    __half* Yh  = H + 4ULL * NBIG;
    __half* YCh = H + 5ULL * NBIG;
    __half* G1h = H + 6ULL * NBIG;
    __half* G2h = H + 7ULL * NBIG;
    __half* Fh  = H + 8ULL * NBIG;
    __half* CH  = H + 9ULL * NBIG;
    __half* KCh = CH + NSMALL;
    __half* VCh = CH + 2ULL * NSMALL;
    __half* WT  = CH + 3ULL * NSMALL;

    const int SMEM_SA = (128 + 128 + 64 + 64) * SAS * 2;                 // 55296
    const int SMEM_CA = (128 * SAS + 128 * CPS + 160 * SAS) * 2 + 320;   // 64320
    cudaFuncSetAttribute(self_attn_mma,
                         cudaFuncAttributeMaxDynamicSharedMemorySize, SMEM_SA);
    cudaFuncSetAttribute(cross_attn_mma,
                         cudaFuncAttributeMaxDynamicSharedMemorySize, SMEM_CA);

    // prep
    const int chunks = NBIG / 8 + NSMALL / 8;
    convert_xc_kernel<<<(chunks + 255) / 256, 256>>>(x, c, XH, CH);
    transpose_w_kernel<<<dim3(16, 16, 8), dim3(32, 8)>>>(
        Wq, Wk, Wv, Wkc, Wvc, Wg1, Wg2, Wp, WT);

    // projections
    proj_kernel<<<400, 256>>>(XH, CH, WT, bq, bk, bv, bkc, bvc,
                              Qh, Kh, Vh, KCh, VCh);

    // attention
    self_attn_mma<<<dim3(16, BATCH * HEADS), 256, SMEM_SA>>>(Qh, Kh, Vh, Yh);
    cross_attn_mma<<<dim3(16, BATCH * HEADS), 256, SMEM_CA>>>(Qh, KCh, VCh, pad, YCh);

    // gates + fuse + output
    gates_kernel<<<256, 256>>>(Yh, YCh, WT, bg1, bg2, G1h, G2h);
    gate_fuse_kernel<<<NBIG / 8 / 256, 256>>>(G1h, G2h, Yh, YCh, Fh);
    final_gemm_kernel<<<128, 256>>>(Fh, WT, bp, out);
}

// round 6
// speedup vs baseline: 3.6336x; 1.0496x over previous
#include <cuda_runtime.h>
#include <cuda_fp16.h>
#include <math.h>
#include <stdint.h>

#define BATCH 2
#define TLEN 2048
#define MLEN 77
#define CDIM 512
#define HEADS 8
#define BT 4096
#define NBIG 2097152
#define NSMALL 78848
#define MSMALL 154
#define WTSZ 262144
#define QSCALE 0.18033688011112042f   // 0.125 * log2(e)
#define NEGB (-30000.0f)

// fp16 scratch: XH,Q,K,V,Y,YC,G1,G2,F (9*NBIG), CH,KC,VC (3*NSMALL), WT[8]
__device__ __half g_h[9ULL * NBIG + 3ULL * NSMALL + 8ULL * WTSZ];

// ---------------------------------------------------------------------------
// helpers
// ---------------------------------------------------------------------------
__device__ __forceinline__ uint32_t smem_u32(const void* p) {
    return (uint32_t)__cvta_generic_to_shared(p);
}
__device__ __forceinline__ void ldsm_x4(uint32_t& r0, uint32_t& r1,
                                        uint32_t& r2, uint32_t& r3, uint32_t a) {
    asm volatile("ldmatrix.sync.aligned.m8n8.x4.shared.b16 {%0,%1,%2,%3}, [%4];"
                 : "=r"(r0), "=r"(r1), "=r"(r2), "=r"(r3) : "r"(a));
}
__device__ __forceinline__ void ldsm_x4_t(uint32_t& r0, uint32_t& r1,
                                          uint32_t& r2, uint32_t& r3, uint32_t a) {
    asm volatile("ldmatrix.sync.aligned.m8n8.x4.trans.shared.b16 {%0,%1,%2,%3}, [%4];"
                 : "=r"(r0), "=r"(r1), "=r"(r2), "=r"(r3) : "r"(a));
}
__device__ __forceinline__ void mma16816(float (&d)[4],
    uint32_t a0, uint32_t a1, uint32_t a2, uint32_t a3, uint32_t b0, uint32_t b1) {
    asm volatile(
        "mma.sync.aligned.m16n8k16.row.col.f32.f16.f16.f32 "
        "{%0,%1,%2,%3}, {%4,%5,%6,%7}, {%8,%9}, {%0,%1,%2,%3};\n"
        : "+f"(d[0]), "+f"(d[1]), "+f"(d[2]), "+f"(d[3])
        : "r"(a0), "r"(a1), "r"(a2), "r"(a3), "r"(b0), "r"(b1));
}
__device__ __forceinline__ float ex2(float x) {
    float r;
    asm("ex2.approx.ftz.f32 %0, %1;" : "=f"(r) : "f"(x));
    return r;
}
__device__ __forceinline__ void cp16(uint32_t s, const void* g) {
    asm volatile("cp.async.cg.shared.global [%0], [%1], 16;" :: "r"(s), "l"(g));
}
__device__ __forceinline__ void cp_commit() {
    asm volatile("cp.async.commit_group;");
}
template <int N>
__device__ __forceinline__ void cp_wait() {
    asm volatile("cp.async.wait_group %0;" :: "n"(N));
}

// ---------------------------------------------------------------------------
// prep: x, c -> fp16
// ---------------------------------------------------------------------------
__global__ __launch_bounds__(256) void convert_xc_kernel(
    const float* __restrict__ x, const float* __restrict__ c,
    __half* __restrict__ xh, __half* __restrict__ ch)
{
    const int i = blockIdx.x * 256 + threadIdx.x;
    const float* src;
    __half* dst;
    int k;
    if (i < NBIG / 8) { src = x; dst = xh; k = i; }
    else if (i < (NBIG + NSMALL) / 8) { src = c; dst = ch; k = i - NBIG / 8; }
    else return;
    const float4 f0 = reinterpret_cast<const float4*>(src)[k * 2];
    const float4 f1 = reinterpret_cast<const float4*>(src)[k * 2 + 1];
    __half2 h[4];
    h[0] = __floats2half2_rn(f0.x, f0.y);
    h[1] = __floats2half2_rn(f0.z, f0.w);
    h[2] = __floats2half2_rn(f1.x, f1.y);
    h[3] = __floats2half2_rn(f1.z, f1.w);
    reinterpret_cast<uint4*>(dst)[k] = *reinterpret_cast<uint4*>(h);
}

// prep: W[k][n] fp32 -> Wt[n][k] fp16 (8 matrices)
__global__ void transpose_w_kernel(
    const float* __restrict__ W0, const float* __restrict__ W1,
    const float* __restrict__ W2, const float* __restrict__ W3,
    const float* __restrict__ W4, const float* __restrict__ W5,
    const float* __restrict__ W6, const float* __restrict__ W7,
    __half* __restrict__ Wt)
{
    __shared__ __half t[32][33];
    const int z = blockIdx.z;
    const float* src = (z == 0) ? W0 : (z == 1) ? W1 : (z == 2) ? W2 : (z == 3) ? W3
                     : (z == 4) ? W4 : (z == 5) ? W5 : (z == 6) ? W6 : W7;
    __half* dst = Wt + (size_t)z * WTSZ;
    const int tx = threadIdx.x, ty = threadIdx.y;
    const int k0 = blockIdx.y * 32, n0 = blockIdx.x * 32;
#pragma unroll
    for (int i = 0; i < 4; ++i)
        t[ty + i * 8][tx] = __float2half_rn(src[(size_t)(k0 + ty + i * 8) * 512 + n0 + tx]);
    __syncthreads();
#pragma unroll
    for (int i = 0; i < 4; ++i)
        dst[(size_t)(n0 + ty + i * 8) * 512 + k0 + tx] = t[tx][ty + i * 8];
}

// ---------------------------------------------------------------------------
// fp16 GEMM core (unchanged from R5): 128x128 tile, BK=32, dbuf registers
// ---------------------------------------------------------------------------
__device__ __forceinline__ void gemm_core(
    const __half* __restrict__ A, const __half* __restrict__ Wt,
    const float* __restrict__ bias,
    __half* __restrict__ outh, float* __restrict__ outf, float oscale,
    int Mrows, int m0, int n0)
{
    __shared__ __half sA[2][128][40];
    __shared__ __half sB[2][128][40];

    const int tid = threadIdx.x;
    const int lane = tid & 31;
    const int wid = tid >> 5;
    const int wm = (wid >> 1) * 32;
    const int wn = (wid & 1) * 64;
    const int g = lane >> 2;
    const int tg = lane & 3;

    const int ar = tid >> 1;
    const int ak = (tid & 1) * 16;
    const bool aok = (m0 + ar) < Mrows;
    const __half* aptr = A + (size_t)(m0 + ar) * 512 + ak;
    const __half* bptr = Wt + (size_t)(n0 + ar) * 512 + ak;

    const int arow = wm + (lane & 15);
    const int acol = (lane >> 4) * 8;
    const int brow = wn + ((lane >> 3) & 1) * 8 + (lane & 7);
    const int bcol = (lane >> 4) * 8;

    float acc[2][8][4];
#pragma unroll
    for (int im = 0; im < 2; ++im)
#pragma unroll
        for (int in = 0; in < 8; ++in)
#pragma unroll
            for (int j = 0; j < 4; ++j) acc[im][in][j] = 0.f;

    uint4 ra0, ra1, rb0, rb1;
    const uint4 z4 = make_uint4(0, 0, 0, 0);

    auto load_stage = [&](int k0) {
        ra0 = aok ? *reinterpret_cast<const uint4*>(aptr + k0) : z4;
        ra1 = aok ? *reinterpret_cast<const uint4*>(aptr + k0 + 8) : z4;
        rb0 = *reinterpret_cast<const uint4*>(bptr + k0);
        rb1 = *reinterpret_cast<const uint4*>(bptr + k0 + 8);
    };
    auto store_stage = [&](int buf) {
        *reinterpret_cast<uint4*>(&sA[buf][ar][ak]) = ra0;
        *reinterpret_cast<uint4*>(&sA[buf][ar][ak + 8]) = ra1;
        *reinterpret_cast<uint4*>(&sB[buf][ar][ak]) = rb0;
        *reinterpret_cast<uint4*>(&sB[buf][ar][ak + 8]) = rb1;
    };

    load_stage(0);
    store_stage(0);
    __syncthreads();

#pragma unroll 1
    for (int it = 0; it < 16; ++it) {
        const int buf = it & 1;
        if (it < 15) load_stage((it + 1) * 32);

#pragma unroll
        for (int kc = 0; kc < 32; kc += 16) {
            uint32_t a[2][4];
#pragma unroll
            for (int im = 0; im < 2; ++im)
                ldsm_x4(a[im][0], a[im][1], a[im][2], a[im][3],
                        smem_u32(&sA[buf][arow + im * 16][acol + kc]));
#pragma unroll
            for (int nq = 0; nq < 4; ++nq) {
                uint32_t b0, b1, b2, b3;
                ldsm_x4(b0, b1, b2, b3,
                        smem_u32(&sB[buf][brow + nq * 16][bcol + kc]));
#pragma unroll
                for (int im = 0; im < 2; ++im) {
                    mma16816(acc[im][2 * nq],     a[im][0], a[im][1], a[im][2], a[im][3], b0, b2);
                    mma16816(acc[im][2 * nq + 1], a[im][0], a[im][1], a[im][2], a[im][3], b1, b3);
                }
            }
        }
        if (it < 15) {
            store_stage(1 - buf);
            __syncthreads();
        }
    }

#pragma unroll
    for (int in = 0; in < 8; ++in) {
        const int col = n0 + wn + in * 8 + tg * 2;
        const float2 bb = *reinterpret_cast<const float2*>(bias + col);
#pragma unroll
        for (int im = 0; im < 2; ++im) {
            const int r0 = m0 + wm + im * 16 + g;
            const int r1 = r0 + 8;
            if (r0 < Mrows) {
                const float v0 = (acc[im][in][0] + bb.x) * oscale;
                const float v1 = (acc[im][in][1] + bb.y) * oscale;
                if (outh)
                    *reinterpret_cast<__half2*>(outh + (size_t)r0 * 512 + col) =
                        __floats2half2_rn(v0, v1);
                else
                    *reinterpret_cast<float2*>(outf + (size_t)r0 * 512 + col) =
                        make_float2(v0, v1);
            }
            if (r1 < Mrows) {
                const float v2 = (acc[im][in][2] + bb.x) * oscale;
                const float v3 = (acc[im][in][3] + bb.y) * oscale;
                if (outh)
                    *reinterpret_cast<__half2*>(outh + (size_t)r1 * 512 + col) =
                        __floats2half2_rn(v2, v3);
                else
                    *reinterpret_cast<float2*>(outf + (size_t)r1 * 512 + col) =
                        make_float2(v2, v3);
            }
        }
    }
}

// projections: Q(pre-scaled),K,V (3x128) + KC,VC (2x8) = 400 blocks
__global__ __launch_bounds__(256) void proj_kernel(
    const __half* __restrict__ xh, const __half* __restrict__ ch,
    const __half* __restrict__ Wt,
    const float* __restrict__ bq, const float* __restrict__ bk,
    const float* __restrict__ bv, const float* __restrict__ bkc,
    const float* __restrict__ bvc,
    __half* __restrict__ Qh, __half* __restrict__ Kh, __half* __restrict__ Vh,
    __half* __restrict__ KCh, __half* __restrict__ VCh)
{
    const int bid = blockIdx.x;
    const __half *A, *W;
    const float* bias;
    __half* out;
    float oscale = 1.0f;
    int Mrows, m0, n0;
    if (bid < 384) {
        const int t = bid / 128, l = bid % 128;
        m0 = (l >> 2) * 128;
        n0 = (l & 3) * 128;
        A = xh; Mrows = BT;
        W = Wt + (size_t)t * WTSZ;
        bias = (t == 0) ? bq : ((t == 1) ? bk : bv);
        out = (t == 0) ? Qh : ((t == 1) ? Kh : Vh);
        if (t == 0) oscale = QSCALE;
    } else {
        const int r = bid - 384;
        const int t = r / 8, l = r % 8;
        m0 = (l >> 2) * 128;
        n0 = (l & 3) * 128;
        A = ch; Mrows = MSMALL;
        W = Wt + (size_t)(3 + t) * WTSZ;
        bias = t ? bvc : bkc;
        out = t ? VCh : KCh;
    }
    gemm_core(A, W, bias, out, nullptr, oscale, Mrows, m0, n0);
}

__global__ __launch_bounds__(256) void gates_kernel(
    const __half* __restrict__ Yh, const __half* __restrict__ YCh,
    const __half* __restrict__ Wt,
    const float* __restrict__ bg1, const float* __restrict__ bg2,
    __half* __restrict__ G1, __half* __restrict__ G2)
{
    const int bid = blockIdx.x;
    const int t = bid >> 7;
    const int l = bid & 127;
    gemm_core(t ? YCh : Yh, Wt + (size_t)(5 + t) * WTSZ, t ? bg2 : bg1,
              t ? G2 : G1, nullptr, 1.0f, BT, (l >> 2) * 128, (l & 3) * 128);
}

__global__ __launch_bounds__(256) void final_gemm_kernel(
    const __half* __restrict__ F, const __half* __restrict__ Wt,
    const float* __restrict__ bp, float* __restrict__ out)
{
    const int l = blockIdx.x;
    gemm_core(F, Wt + 7ULL * WTSZ, bp, nullptr, out, 1.0f, BT,
              (l >> 2) * 128, (l & 3) * 128);
}

// ---------------------------------------------------------------------------
// Merged attention kernel. grid (32, B*H):
//   x in [0,16)  : causal self-attn, qb = 15 - x (heavy first), cp.async dbuf
//   x in [16,32) : cross-attn, qb = x - 16
// 256 threads. dynamic smem 73728 B.
// ---------------------------------------------------------------------------
#define SAS 72
#define CPS 88

__global__ __launch_bounds__(256) void attn_kernel(
    const __half* __restrict__ Q, const __half* __restrict__ K,
    const __half* __restrict__ V,
    const __half* __restrict__ Kc, const __half* __restrict__ Vc,
    const int* __restrict__ pad,
    __half* __restrict__ Y, __half* __restrict__ Yc)
{
    extern __shared__ __half smh[];

    const int bh = blockIdx.y;
    const int b = bh >> 3;
    const int h = bh & 7;
    const int tid = threadIdx.x;
    const int lane = tid & 31;
    const int wid = tid >> 5;
    const int g = lane >> 2;
    const int tg = lane & 3;
    const int wm = wid * 16;

    const size_t qbase = ((size_t)b * TLEN) * CDIM + h * 64;

    // common ldmatrix lane mappings
    const int arow = wm + (lane & 15);
    const int acol = (lane >> 4) * 8;
    const int brow = ((lane >> 3) & 1) * 8 + (lane & 7);
    const int bcol = (lane >> 4) * 8;
    const int vrow = (lane & 7) + ((lane >> 4) & 1) * 8;
    const int vcol = ((lane >> 3) & 1) * 8;
    const int rA = wm + g;

    if (blockIdx.x < 16) {
        // =================== causal self-attention ===================
        __half* sQ = smh;                     // [128][72]
        __half* sP = sQ + 128 * SAS;          // [128][72]
        __half* sK = sP + 128 * SAS;          // [2][64][72]
        __half* sV = sK + 2 * 64 * SAS;       // [2][64][72]

        const int qb = 15 - (int)blockIdx.x;

        // stage Q (128 x 64 halves)
        {
            const int r = tid >> 1, cb = (tid & 1) * 32;
            const uint4* src = reinterpret_cast<const uint4*>(
                Q + qbase + (size_t)(qb * 128 + r) * CDIM + cb);
            uint4* dst = reinterpret_cast<uint4*>(&sQ[r * SAS + cb]);
            dst[0] = src[0]; dst[1] = src[1]; dst[2] = src[2]; dst[3] = src[3];
        }

        const int kvr = tid >> 2, kvc = (tid & 3) * 16;

        auto prefetch = [&](int jt, int buf) {
            const size_t gofs = qbase + (size_t)(jt * 64 + kvr) * CDIM + kvc;
            const uint32_t kd = smem_u32(&sK[(buf * 64 + kvr) * SAS + kvc]);
            const uint32_t vd = smem_u32(&sV[(buf * 64 + kvr) * SAS + kvc]);
            cp16(kd, K + gofs);
            cp16(kd + 16, K + gofs + 8);
            cp16(vd, V + gofs);
            cp16(vd + 16, V + gofs + 8);
        };

        float o[8][4];
#pragma unroll
        for (int in = 0; in < 8; ++in)
#pragma unroll
            for (int j = 0; j < 4; ++j) o[in][j] = 0.f;
        float mrow[2] = {NEGB, NEGB};
        float lrow[2] = {0.f, 0.f};

        const int qrA = qb * 128 + rA;
        const int qrB = qrA + 8;
        const int nIter = 2 * (qb + 1);

        prefetch(0, 0);
        cp_commit();

#pragma unroll 1
        for (int jt = 0; jt < nIter; ++jt) {
            const int buf = jt & 1;
            if (jt + 1 < nIter) {
                prefetch(jt + 1, buf ^ 1);
                cp_commit();
                cp_wait<1>();
            } else {
                cp_wait<0>();
            }
            __syncthreads();

            // S = Q @ K^T (Q pre-scaled by 0.125*log2e)
            float s[8][4];
#pragma unroll
            for (int in = 0; in < 8; ++in)
#pragma unroll
                for (int j = 0; j < 4; ++j) s[in][j] = 0.f;

#pragma unroll
            for (int kc = 0; kc < 64; kc += 16) {
                uint32_t a0, a1, a2, a3;
                ldsm_x4(a0, a1, a2, a3, smem_u32(&sQ[arow * SAS + acol + kc]));
#pragma unroll
                for (int nq = 0; nq < 4; ++nq) {
                    uint32_t b0, b1, b2, b3;
                    ldsm_x4(b0, b1, b2, b3,
                            smem_u32(&sK[(buf * 64 + nq * 16 + brow) * SAS + bcol + kc]));
                    mma16816(s[2 * nq],     a0, a1, a2, a3, b0, b2);
                    mma16816(s[2 * nq + 1], a0, a1, a2, a3, b1, b3);
                }
            }

            if (jt >= 2 * qb) {
#pragma unroll
                for (int in = 0; in < 8; ++in) {
                    const int cj = jt * 64 + in * 8 + tg * 2;
                    if (cj     > qrA) s[in][0] = NEGB;
                    if (cj + 1 > qrA) s[in][1] = NEGB;
                    if (cj     > qrB) s[in][2] = NEGB;
                    if (cj + 1 > qrB) s[in][3] = NEGB;
                }
            }

            float rmA = NEGB, rmB = NEGB;
#pragma unroll
            for (int in = 0; in < 8; ++in) {
                rmA = fmaxf(rmA, fmaxf(s[in][0], s[in][1]));
                rmB = fmaxf(rmB, fmaxf(s[in][2], s[in][3]));
            }
            rmA = fmaxf(rmA, __shfl_xor_sync(0xffffffffu, rmA, 1));
            rmA = fmaxf(rmA, __shfl_xor_sync(0xffffffffu, rmA, 2));
            rmB = fmaxf(rmB, __shfl_xor_sync(0xffffffffu, rmB, 1));
            rmB = fmaxf(rmB, __shfl_xor_sync(0xffffffffu, rmB, 2));

            const float mA = fmaxf(mrow[0], rmA);
            const float mB = fmaxf(mrow[1], rmB);
            const float cA = ex2(mrow[0] - mA);
            const float cB = ex2(mrow[1] - mB);

            float rsA = 0.f, rsB = 0.f;
#pragma unroll
            for (int in = 0; in < 8; ++in) {
                const float p0 = ex2(s[in][0] - mA);
                const float p1 = ex2(s[in][1] - mA);
                const float p2 = ex2(s[in][2] - mB);
                const float p3 = ex2(s[in][3] - mB);
                rsA += p0 + p1;
                rsB += p2 + p3;
                const int col = in * 8 + tg * 2;
                *reinterpret_cast<__half2*>(&sP[rA * SAS + col]) = __floats2half2_rn(p0, p1);
                *reinterpret_cast<__half2*>(&sP[(rA + 8) * SAS + col]) = __floats2half2_rn(p2, p3);
            }
            rsA += __shfl_xor_sync(0xffffffffu, rsA, 1);
            rsA += __shfl_xor_sync(0xffffffffu, rsA, 2);
            rsB += __shfl_xor_sync(0xffffffffu, rsB, 1);
            rsB += __shfl_xor_sync(0xffffffffu, rsB, 2);

            lrow[0] = lrow[0] * cA + rsA;
            lrow[1] = lrow[1] * cB + rsB;
            mrow[0] = mA;
            mrow[1] = mB;

#pragma unroll
            for (int in = 0; in < 8; ++in) {
                o[in][0] *= cA; o[in][1] *= cA;
                o[in][2] *= cB; o[in][3] *= cB;
            }
            __syncwarp();

            // O += P @ V
#pragma unroll
            for (int kc = 0; kc < 64; kc += 16) {
                uint32_t a0, a1, a2, a3;
                ldsm_x4(a0, a1, a2, a3, smem_u32(&sP[arow * SAS + acol + kc]));
#pragma unroll
                for (int dq = 0; dq < 4; ++dq) {
                    uint32_t b0, b1, b2, b3;
                    ldsm_x4_t(b0, b1, b2, b3,
                              smem_u32(&sV[(buf * 64 + kc + vrow) * SAS + dq * 16 + vcol]));
                    mma16816(o[2 * dq],     a0, a1, a2, a3, b0, b2);
                    mma16816(o[2 * dq + 1], a0, a1, a2, a3, b1, b3);
                }
            }
            __syncthreads();
        }

        const float invA = 1.f / lrow[0];
        const float invB = 1.f / lrow[1];
#pragma unroll
        for (int in = 0; in < 8; ++in) {
            const int col = in * 8 + tg * 2;
            *reinterpret_cast<__half2*>(Y + qbase + (size_t)qrA * CDIM + col) =
                __floats2half2_rn(o[in][0] * invA, o[in][1] * invA);
            *reinterpret_cast<__half2*>(Y + qbase + (size_t)qrB * CDIM + col) =
                __floats2half2_rn(o[in][2] * invB, o[in][3] * invB);
        }
    } else {
        // =================== cross-attention ===================
        __half* sQ = smh;                  // [128][72]
        __half* sP = sQ + 128 * SAS;       // [128][88]
        __half* sK = sP + 128 * CPS;       // [80][72]
        __half* sV = sK + 80 * SAS;        // [80][72]
        int* sF = (int*)(sV + 80 * SAS);   // [80]

        const int qb = (int)blockIdx.x - 16;
        const size_t kbase = ((size_t)b * MLEN) * CDIM + h * 64;

        {
            const int r = tid >> 1, cb = (tid & 1) * 32;
            const uint4* src = reinterpret_cast<const uint4*>(
                Q + qbase + (size_t)(qb * 128 + r) * CDIM + cb);
            uint4* dst = reinterpret_cast<uint4*>(&sQ[r * SAS + cb]);
            dst[0] = src[0]; dst[1] = src[1]; dst[2] = src[2]; dst[3] = src[3];
        }
        {
            const int r = tid >> 1, cb = (tid & 1) * 32;
            if (r < 80) {
                uint4 kv0, kv1, kv2, kv3, vv0, vv1, vv2, vv3;
                if (r < MLEN) {
                    const uint4* ks = reinterpret_cast<const uint4*>(Kc + kbase + (size_t)r * CDIM + cb);
                    const uint4* vs = reinterpret_cast<const uint4*>(Vc + kbase + (size_t)r * CDIM + cb);
                    kv0 = ks[0]; kv1 = ks[1]; kv2 = ks[2]; kv3 = ks[3];
                    vv0 = vs[0]; vv1 = vs[1]; vv2 = vs[2]; vv3 = vs[3];
                } else {
                    kv0 = kv1 = kv2 = kv3 = make_uint4(0, 0, 0, 0);
                    vv0 = vv1 = vv2 = vv3 = kv0;
                }
                uint4* kd = reinterpret_cast<uint4*>(&sK[r * SAS + cb]);
                uint4* vd = reinterpret_cast<uint4*>(&sV[r * SAS + cb]);
                kd[0] = kv0; kd[1] = kv1; kd[2] = kv2; kd[3] = kv3;
                vd[0] = vv0; vd[1] = vv1; vd[2] = vv2; vd[3] = vv3;
            }
        }
        if (tid < 80) sF[tid] = (tid < MLEN) ? pad[b * MLEN + tid] : 0;
        __syncthreads();

        float s[10][4];
#pragma unroll
        for (int in = 0; in < 10; ++in)
#pragma unroll
            for (int j = 0; j < 4; ++j) s[in][j] = 0.f;

#pragma unroll
        for (int kc = 0; kc < 64; kc += 16) {
            uint32_t a0, a1, a2, a3;
            ldsm_x4(a0, a1, a2, a3, smem_u32(&sQ[arow * SAS + acol + kc]));
#pragma unroll
            for (int nq = 0; nq < 5; ++nq) {
                uint32_t b0, b1, b2, b3;
                ldsm_x4(b0, b1, b2, b3,
                        smem_u32(&sK[(nq * 16 + brow) * SAS + bcol + kc]));
                mma16816(s[2 * nq],     a0, a1, a2, a3, b0, b2);
                mma16816(s[2 * nq + 1], a0, a1, a2, a3, b1, b3);
            }
        }

#pragma unroll
        for (int in = 0; in < 10; ++in) {
            const int cj = in * 8 + tg * 2;
            if (sF[cj] == 0)     { s[in][0] = NEGB; s[in][2] = NEGB; }
            if (sF[cj + 1] == 0) { s[in][1] = NEGB; s[in][3] = NEGB; }
        }

        float rmA = NEGB, rmB = NEGB;
#pragma unroll
        for (int in = 0; in < 10; ++in) {
            rmA = fmaxf(rmA, fmaxf(s[in][0], s[in][1]));
            rmB = fmaxf(rmB, fmaxf(s[in][2], s[in][3]));
        }
        rmA = fmaxf(rmA, __shfl_xor_sync(0xffffffffu, rmA, 1));
        rmA = fmaxf(rmA, __shfl_xor_sync(0xffffffffu, rmA, 2));
        rmB = fmaxf(rmB, __shfl_xor_sync(0xffffffffu, rmB, 1));
        rmB = fmaxf(rmB, __shfl_xor_sync(0xffffffffu, rmB, 2));

        float rsA = 0.f, rsB = 0.f;
#pragma unroll
        for (int in = 0; in < 10; ++in) {
            const float p0 = ex2(s[in][0] - rmA);
            const float p1 = ex2(s[in][1] - rmA);
            const float p2 = ex2(s[in][2] - rmB);
            const float p3 = ex2(s[in][3] - rmB);
            rsA += p0 + p1;
            rsB += p2 + p3;
            const int col = in * 8 + tg * 2;
            *reinterpret_cast<__half2*>(&sP[rA * CPS + col]) = __floats2half2_rn(p0, p1);
            *reinterpret_cast<__half2*>(&sP[(rA + 8) * CPS + col]) = __floats2half2_rn(p2, p3);
        }
        rsA += __shfl_xor_sync(0xffffffffu, rsA, 1);
        rsA += __shfl_xor_sync(0xffffffffu, rsA, 2);
        rsB += __shfl_xor_sync(0xffffffffu, rsB, 1);
        rsB += __shfl_xor_sync(0xffffffffu, rsB, 2);
        __syncwarp();

        float o[8][4];
#pragma unroll
        for (int in = 0; in < 8; ++in)
#pragma unroll
            for (int j = 0; j < 4; ++j) o[in][j] = 0.f;

#pragma unroll
        for (int kc = 0; kc < 80; kc += 16) {
            uint32_t a0, a1, a2, a3;
            ldsm_x4(a0, a1, a2, a3, smem_u32(&sP[arow * CPS + acol + kc]));
#pragma unroll
            for (int dq = 0; dq < 4; ++dq) {
                uint32_t b0, b1, b2, b3;
                ldsm_x4_t(b0, b1, b2, b3,
                          smem_u32(&sV[(kc + vrow) * SAS + dq * 16 + vcol]));
                mma16816(o[2 * dq],     a0, a1, a2, a3, b0, b2);
                mma16816(o[2 * dq + 1], a0, a1, a2, a3, b1, b3);
            }
        }

        const float invA = (rsA > 0.f) ? (1.f / rsA) : 0.f;
        const float invB = (rsB > 0.f) ? (1.f / rsB) : 0.f;
        const int qrA = qb * 128 + rA;
        const int qrB = qrA + 8;
#pragma unroll
        for (int in = 0; in < 8; ++in) {
            const int col = in * 8 + tg * 2;
            *reinterpret_cast<__half2*>(Yc + qbase + (size_t)qrA * CDIM + col) =
                __floats2half2_rn(o[in][0] * invA, o[in][1] * invA);
            *reinterpret_cast<__half2*>(Yc + qbase + (size_t)qrB * CDIM + col) =
                __floats2half2_rn(o[in][2] * invB, o[in][3] * invB);
        }
    }
}

// ---------------------------------------------------------------------------
// fused = sigmoid(g1) * yc + sigmoid(g2) * y  (fp16 in/out)
// ---------------------------------------------------------------------------
__device__ __forceinline__ float sigf(float x) {
    return 1.f / (1.f + __expf(-x));
}

__global__ __launch_bounds__(256) void gate_fuse_kernel(
    const __half* __restrict__ g1, const __half* __restrict__ g2,
    const __half* __restrict__ y, const __half* __restrict__ yc,
    __half* __restrict__ f)
{
    const int i = blockIdx.x * 256 + threadIdx.x;
    const uint4 ua = reinterpret_cast<const uint4*>(g1)[i];
    const uint4 ub = reinterpret_cast<const uint4*>(g2)[i];
    const uint4 uy = reinterpret_cast<const uint4*>(y)[i];
    const uint4 uc = reinterpret_cast<const uint4*>(yc)[i];
    const __half2* ha = reinterpret_cast<const __half2*>(&ua);
    const __half2* hb = reinterpret_cast<const __half2*>(&ub);
    const __half2* hy = reinterpret_cast<const __half2*>(&uy);
    const __half2* hc = reinterpret_cast<const __half2*>(&uc);
    __half2 ho[4];
#pragma unroll
    for (int k = 0; k < 4; ++k) {
        const float2 a = __half22float2(ha[k]);
        const float2 bg = __half22float2(hb[k]);
        const float2 yv = __half22float2(hy[k]);
        const float2 yw = __half22float2(hc[k]);
        ho[k] = __floats2half2_rn(sigf(a.x) * yw.x + sigf(bg.x) * yv.x,
                                  sigf(a.y) * yw.y + sigf(bg.y) * yv.y);
    }
    reinterpret_cast<uint4*>(f)[i] = *reinterpret_cast<uint4*>(ho);
}

// ---------------------------------------------------------------------------
// Launch
// ---------------------------------------------------------------------------
extern "C" void kernel_launch(void* const* d_in, const int* in_sizes, int n_in,
                              void* d_out, int out_size)
{
    const float* x  = (const float*)d_in[0];
    const float* c  = (const float*)d_in[1];
    const int* pad  = (const int*)d_in[3];
    const float* Wq = (const float*)d_in[4];
    const float* bq = (const float*)d_in[5];
    const float* Wk = (const float*)d_in[6];
    const float* bk = (const float*)d_in[7];
    const float* Wv = (const float*)d_in[8];
    const float* bv = (const float*)d_in[9];
    const float* Wkc = (const float*)d_in[10];
    const float* bkc = (const float*)d_in[11];
    const float* Wvc = (const float*)d_in[12];
    const float* bvc = (const float*)d_in[13];
    const float* Wg1 = (const float*)d_in[14];
    const float* bg1 = (const float*)d_in[15];
    const float* Wg2 = (const float*)d_in[16];
    const float* bg2 = (const float*)d_in[17];
    const float* Wp = (const float*)d_in[18];
    const float* bp = (const float*)d_in[19];
    float* out = (float*)d_out;

    __half* H = nullptr;
    cudaGetSymbolAddress((void**)&H, g_h);
    __half* XH  = H + 0ULL * NBIG;
    __half* Qh  = H + 1ULL * NBIG;
    __half* Kh  = H + 2ULL * NBIG;
    __half* Vh  = H + 3ULL * NBIG;
    __half* Yh  = H + 4ULL * NBIG;
    __half* YCh = H + 5ULL * NBIG;
    __half* G1h = H + 6ULL * NBIG;
    __half* G2h = H + 7ULL * NBIG;
    __half* Fh  = H + 8ULL * NBIG;
    __half* CH  = H + 9ULL * NBIG;
    __half* KCh = CH + NSMALL;
    __half* VCh = CH + 2ULL * NSMALL;
    __half* WT  = CH + 3ULL * NSMALL;

    // self: (128+128+2*64+2*64)*72 halves = 73728 B ; cross fits inside
    const int SMEM_AT = (128 * SAS + 128 * SAS + 128 * SAS + 128 * SAS) * 2; // 73728
    cudaFuncSetAttribute(attn_kernel,
                         cudaFuncAttributeMaxDynamicSharedMemorySize, SMEM_AT);

    const int chunks = NBIG / 8 + NSMALL / 8;
    convert_xc_kernel<<<(chunks + 255) / 256, 256>>>(x, c, XH, CH);
    transpose_w_kernel<<<dim3(16, 16, 8), dim3(32, 8)>>>(
        Wq, Wk, Wv, Wkc, Wvc, Wg1, Wg2, Wp, WT);

    proj_kernel<<<400, 256>>>(XH, CH, WT, bq, bk, bv, bkc, bvc,
                              Qh, Kh, Vh, KCh, VCh);

    attn_kernel<<<dim3(32, BATCH * HEADS), 256, SMEM_AT>>>(
        Qh, Kh, Vh, KCh, VCh, pad, Yh, YCh);

    gates_kernel<<<256, 256>>>(Yh, YCh, WT, bg1, bg2, G1h, G2h);
    gate_fuse_kernel<<<NBIG / 8 / 256, 256>>>(G1h, G2h, Yh, YCh, Fh);
    final_gemm_kernel<<<128, 256>>>(Fh, WT, bp, out);
}